// round 1
// baseline (speedup 1.0000x reference)
#include <cuda_runtime.h>
#include <math.h>

#define Bsz 4
#define SEQ 2048
#define HID 1024
#define NH 16
#define HD 64

// Scratch for Q,K,V in [B][NH][S][HD] layout (d contiguous). ~100 MB total.
__device__ float g_q[Bsz*NH*SEQ*HD];
__device__ float g_k[Bsz*NH*SEQ*HD];
__device__ float g_v[Bsz*NH*SEQ*HD];

// ---------------------------------------------------------------------------
// Kernel 1: fused QKV projection.  X[BS,H] @ {Wq|Wk|Wv}[H,H] + bias
// Tile 64x64, BK=16, 256 threads, 4x4 per thread.
// blockIdx.x in [0,48): 16 col-tiles each for Q, K, V. blockIdx.y: row tiles.
// ---------------------------------------------------------------------------
__global__ __launch_bounds__(256) void qkv_gemm(
    const float* __restrict__ X,
    const float* __restrict__ Wq, const float* __restrict__ bq,
    const float* __restrict__ Wk, const float* __restrict__ bk,
    const float* __restrict__ Wv, const float* __restrict__ bv)
{
    __shared__ float As[16][68];   // [k][m] transposed
    __shared__ float Bs[16][68];   // [k][n]

    const int tid  = threadIdx.x;
    const int row0 = blockIdx.y * 64;           // over B*S = 8192
    const int col  = blockIdx.x * 64;           // over 3*H = 3072
    const int sel  = col / HID;                 // 0=Q 1=K 2=V
    const int ncol = col % HID;                 // multiple of 64

    const float* W    = (sel == 0) ? Wq : (sel == 1) ? Wk : Wv;
    const float* bias = (sel == 0) ? bq : (sel == 1) ? bk : bv;
    float*       dst  = (sel == 0) ? g_q : (sel == 1) ? g_k : g_v;

    const int tm = tid >> 4;        // 0..15
    const int tn = tid & 15;        // 0..15

    float acc[4][4];
#pragma unroll
    for (int i = 0; i < 4; i++)
#pragma unroll
        for (int j = 0; j < 4; j++) acc[i][j] = 0.f;

    const int lr = tid >> 2;           // 0..63 (A row)
    const int lk = (tid & 3) * 4;      // 0,4,8,12 (A k)
    const int wk = tid >> 4;           // 0..15 (B k row)
    const int wn = (tid & 15) * 4;     // 0..60 (B n)

    for (int k0 = 0; k0 < HID; k0 += 16) {
        float4 a4 = *(const float4*)&X[(row0 + lr) * HID + k0 + lk];
        As[lk + 0][lr] = a4.x; As[lk + 1][lr] = a4.y;
        As[lk + 2][lr] = a4.z; As[lk + 3][lr] = a4.w;
        *(float4*)&Bs[wk][wn] = *(const float4*)&W[(k0 + wk) * HID + ncol + wn];
        __syncthreads();
#pragma unroll
        for (int kk = 0; kk < 16; kk++) {
            float4 av = *(float4*)&As[kk][tm * 4];
            float4 bw = *(float4*)&Bs[kk][tn * 4];
            float a[4] = {av.x, av.y, av.z, av.w};
            float b[4] = {bw.x, bw.y, bw.z, bw.w};
#pragma unroll
            for (int i = 0; i < 4; i++)
#pragma unroll
                for (int j = 0; j < 4; j++)
                    acc[i][j] += a[i] * b[j];
        }
        __syncthreads();
    }

    // Epilogue: bias + write to [B][NH][S][HD]
    const int h = ncol / HD;             // block-constant head
    float bvv[4];
#pragma unroll
    for (int j = 0; j < 4; j++) bvv[j] = bias[ncol + tn * 4 + j];
#pragma unroll
    for (int i = 0; i < 4; i++) {
        int r  = row0 + tm * 4 + i;
        int bb = r / SEQ, s = r % SEQ;
        float4 o;
        o.x = acc[i][0] + bvv[0];
        o.y = acc[i][1] + bvv[1];
        o.z = acc[i][2] + bvv[2];
        o.w = acc[i][3] + bvv[3];
        *(float4*)&dst[(((bb * NH + h) * SEQ) + s) * HD + tn * 4] = o;
    }
}

// ---------------------------------------------------------------------------
// Kernel 2: flash attention, fp32. Br=64 q rows/block, Bc=32 keys/iter,
// 128 threads. S-compute mapping: thread (tid/8 -> 4 rows, tid%8 -> 4 cols).
// Softmax/PV mapping: row = tid/2, half = tid%2 (32 d-values each, in regs).
// Row groups of 16 stay within one warp for BOTH mappings -> __syncwarp ok.
// ---------------------------------------------------------------------------
__global__ __launch_bounds__(128) void flash_attn(
    const float* __restrict__ mask, float* __restrict__ out)
{
    const int b  = blockIdx.z;
    const int h  = blockIdx.y;
    const int q0 = blockIdx.x * 64;

    __shared__ float Qs[64][68];
    __shared__ float Ks[32][68];
    __shared__ float Vs[32][68];
    __shared__ float Ss[64][33];

    const int tid = threadIdx.x;
    const float* Qg = g_q + ((size_t)(b * NH + h) * SEQ) * HD;
    const float* Kg = g_k + ((size_t)(b * NH + h) * SEQ) * HD;
    const float* Vg = g_v + ((size_t)(b * NH + h) * SEQ) * HD;
    const float* mk = mask + b * SEQ;

    // Load Q tile 64x64
    {
        int r  = tid >> 4;            // 0..7
        int d4 = (tid & 15) * 4;
#pragma unroll
        for (int rr = 0; rr < 64; rr += 8)
            *(float4*)&Qs[rr + r][d4] = *(const float4*)&Qg[(q0 + rr + r) * HD + d4];
    }

    const int sr0   = (tid >> 3) * 4;   // S rows
    const int sc0   = (tid & 7) * 4;    // S cols
    const int row   = tid >> 1;         // O row
    const int half  = tid & 1;
    const int dbase = half * 32;

    float m_r = -1e30f, l_r = 0.f;
    float O[32];
#pragma unroll
    for (int i = 0; i < 32; i++) O[i] = 0.f;

    const float scale = 0.125f;   // 1/sqrt(64)

    for (int kc = 0; kc < SEQ; kc += 32) {
        __syncthreads();   // prev iter's consumers of Ks/Vs done
        {
            int r  = tid >> 4;
            int d4 = (tid & 15) * 4;
#pragma unroll
            for (int rr = 0; rr < 32; rr += 8) {
                *(float4*)&Ks[rr + r][d4] = *(const float4*)&Kg[(kc + rr + r) * HD + d4];
                *(float4*)&Vs[rr + r][d4] = *(const float4*)&Vg[(kc + rr + r) * HD + d4];
            }
        }
        __syncthreads();

        // S = Q K^T  (4x4 per thread, dot4 inner)
        float acc[4][4];
#pragma unroll
        for (int i = 0; i < 4; i++)
#pragma unroll
            for (int j = 0; j < 4; j++) acc[i][j] = 0.f;
#pragma unroll
        for (int d4 = 0; d4 < 64; d4 += 4) {
            float4 qa[4], kb[4];
#pragma unroll
            for (int i = 0; i < 4; i++) qa[i] = *(float4*)&Qs[sr0 + i][d4];
#pragma unroll
            for (int j = 0; j < 4; j++) kb[j] = *(float4*)&Ks[sc0 + j][d4];
#pragma unroll
            for (int i = 0; i < 4; i++)
#pragma unroll
                for (int j = 0; j < 4; j++)
                    acc[i][j] += qa[i].x * kb[j].x + qa[i].y * kb[j].y
                               + qa[i].z * kb[j].z + qa[i].w * kb[j].w;
        }
#pragma unroll
        for (int j = 0; j < 4; j++) {
            float mv = mk[kc + sc0 + j];
#pragma unroll
            for (int i = 0; i < 4; i++)
                Ss[sr0 + i][sc0 + j] = acc[i][j] * scale + mv;
        }
        __syncwarp();   // S writers of my 16-row group are in my warp

        // Online softmax for my row (pair tid, tid^1 shares the row)
        float tmax = -1e30f;
#pragma unroll
        for (int j = 0; j < 16; j++) tmax = fmaxf(tmax, Ss[row][half * 16 + j]);
        tmax = fmaxf(tmax, __shfl_xor_sync(0xffffffffu, tmax, 1));
        float m_new = fmaxf(m_r, tmax);
        float alpha = __expf(m_r - m_new);
        float psum = 0.f;
#pragma unroll
        for (int j = 0; j < 16; j++) {
            float p = __expf(Ss[row][half * 16 + j] - m_new);
            Ss[row][half * 16 + j] = p;
            psum += p;
        }
        psum += __shfl_xor_sync(0xffffffffu, psum, 1);
        l_r = l_r * alpha + psum;
        m_r = m_new;
#pragma unroll
        for (int i = 0; i < 32; i++) O[i] *= alpha;
        __syncwarp();   // partner's p-writes visible

        // O += P V
#pragma unroll
        for (int c = 0; c < 32; c++) {
            float p = Ss[row][c];
#pragma unroll
            for (int j4 = 0; j4 < 32; j4 += 4) {
                float4 v4 = *(float4*)&Vs[c][dbase + j4];
                O[j4 + 0] += p * v4.x; O[j4 + 1] += p * v4.y;
                O[j4 + 2] += p * v4.z; O[j4 + 3] += p * v4.w;
            }
        }
    }

    // Normalize + write out[b][s][h*64 + d]
    float inv = 1.f / l_r;
    float* op = out + ((size_t)(b * SEQ + q0 + row) * HID) + h * HD + dbase;
#pragma unroll
    for (int j4 = 0; j4 < 32; j4 += 4) {
        float4 o;
        o.x = O[j4 + 0] * inv; o.y = O[j4 + 1] * inv;
        o.z = O[j4 + 2] * inv; o.w = O[j4 + 3] * inv;
        *(float4*)&op[j4] = o;
    }
}

// ---------------------------------------------------------------------------
extern "C" void kernel_launch(void* const* d_in, const int* in_sizes, int n_in,
                              void* d_out, int out_size)
{
    const float* X    = (const float*)d_in[0];
    const float* mask = (const float*)d_in[1];
    const float* Wq   = (const float*)d_in[2];
    const float* bq   = (const float*)d_in[3];
    const float* Wk   = (const float*)d_in[4];
    const float* bk   = (const float*)d_in[5];
    const float* Wv   = (const float*)d_in[6];
    const float* bv   = (const float*)d_in[7];
    float* out = (float*)d_out;

    dim3 g1(48, 128);            // 3072/64 cols, 8192/64 rows
    qkv_gemm<<<g1, 256>>>(X, Wq, bq, Wk, bk, Wv, bv);

    dim3 g2(32, NH, Bsz);        // 2048/64 q-tiles, heads, batch
    flash_attn<<<g2, 128>>>(mask, out);
}

// round 2
// speedup vs baseline: 3.6417x; 3.6417x over previous
#include <cuda_runtime.h>
#include <math.h>

#define Bsz 4
#define SEQ 2048
#define HID 1024
#define NH 16
#define HD 64

// Scratch Q,K,V in [B][NH][S][HD] layout.
__device__ float g_q[Bsz*NH*SEQ*HD];
__device__ float g_k[Bsz*NH*SEQ*HD];
__device__ float g_v[Bsz*NH*SEQ*HD];

// ---------------------------------------------------------------------------
// tf32 helpers
// ---------------------------------------------------------------------------
__device__ __forceinline__ float f2tf(float x) {
    unsigned u;
    asm("cvt.rna.tf32.f32 %0, %1;" : "=r"(u) : "f"(x));
    return __uint_as_float(u);
}
__device__ __forceinline__ unsigned fbits(float x) { return __float_as_uint(x); }

// D += A(16x8,row) * B(8x8,col), tf32 inputs, fp32 accum
__device__ __forceinline__ void mma8(float* c,
                                     unsigned a0, unsigned a1, unsigned a2, unsigned a3,
                                     unsigned b0, unsigned b1) {
    asm volatile(
        "mma.sync.aligned.m16n8k8.row.col.f32.tf32.tf32.f32 "
        "{%0,%1,%2,%3},{%4,%5,%6,%7},{%8,%9},{%0,%1,%2,%3};"
        : "+f"(c[0]), "+f"(c[1]), "+f"(c[2]), "+f"(c[3])
        : "r"(a0), "r"(a1), "r"(a2), "r"(a3), "r"(b0), "r"(b1));
}

// ---------------------------------------------------------------------------
// Kernel 1: fused QKV projection, tf32 MMA.
// Tile 128x64 (BN=64 == one head), BK=16, 128 threads (4 warps, 2x2).
// blockIdx.x in [0,48): 16 col-tiles for each of Q,K,V. blockIdx.y: 64 row tiles.
// ---------------------------------------------------------------------------
__global__ __launch_bounds__(128) void qkv_gemm(
    const float* __restrict__ X,
    const float* __restrict__ Wq, const float* __restrict__ bq,
    const float* __restrict__ Wk, const float* __restrict__ bk,
    const float* __restrict__ Wv, const float* __restrict__ bv)
{
    __shared__ float As[128][20];   // [m][k], stride 20 -> conflict-free frag loads
    __shared__ float Bs[16][72];    // [k][n], stride 72 -> conflict-free frag loads

    const int tid  = threadIdx.x;
    const int warp = tid >> 5;
    const int lane = tid & 31;
    const int g    = lane >> 2;     // group id 0..7
    const int tig  = lane & 3;      // thread in group

    const int row0   = blockIdx.y * 128;     // over B*S = 8192
    const int colblk = blockIdx.x;           // 0..47
    const int sel    = colblk >> 4;          // 0=Q 1=K 2=V
    const int h      = colblk & 15;          // head
    const int ncol   = h * 64;

    const float* W    = (sel == 0) ? Wq : (sel == 1) ? Wk : Wv;
    const float* bias = (sel == 0) ? bq : (sel == 1) ? bk : bv;
    float*       dst  = (sel == 0) ? g_q : (sel == 1) ? g_k : g_v;

    const int wm = (warp >> 1) * 64;    // warp m offset (0/64)
    const int wn = (warp & 1) * 32;     // warp n offset (0/32)

    float acc[4][4][4];
#pragma unroll
    for (int i = 0; i < 4; i++)
#pragma unroll
        for (int j = 0; j < 4; j++)
#pragma unroll
            for (int k = 0; k < 4; k++) acc[i][j][k] = 0.f;

    const int arow = tid >> 2;          // 0..31
    const int ac4  = (tid & 3) * 4;     // 0,4,8,12
    const int brow = tid >> 4;          // 0..7
    const int bc4  = (tid & 15) * 4;    // 0..60

    for (int k0 = 0; k0 < HID; k0 += 16) {
#pragma unroll
        for (int i = 0; i < 4; i++) {
            int r = arow + i * 32;
            float4 v = *(const float4*)&X[(size_t)(row0 + r) * HID + k0 + ac4];
            As[r][ac4 + 0] = f2tf(v.x); As[r][ac4 + 1] = f2tf(v.y);
            As[r][ac4 + 2] = f2tf(v.z); As[r][ac4 + 3] = f2tf(v.w);
        }
#pragma unroll
        for (int i = 0; i < 2; i++) {
            int r = brow + i * 8;
            float4 v = *(const float4*)&W[(size_t)(k0 + r) * HID + ncol + bc4];
            Bs[r][bc4 + 0] = f2tf(v.x); Bs[r][bc4 + 1] = f2tf(v.y);
            Bs[r][bc4 + 2] = f2tf(v.z); Bs[r][bc4 + 3] = f2tf(v.w);
        }
        __syncthreads();

#pragma unroll
        for (int ks = 0; ks < 2; ks++) {
            const int kb = ks * 8;
            unsigned a[4][4];
#pragma unroll
            for (int mt = 0; mt < 4; mt++) {
                int r = wm + mt * 16;
                a[mt][0] = fbits(As[r + g    ][kb + tig    ]);
                a[mt][1] = fbits(As[r + g + 8][kb + tig    ]);
                a[mt][2] = fbits(As[r + g    ][kb + tig + 4]);
                a[mt][3] = fbits(As[r + g + 8][kb + tig + 4]);
            }
            unsigned b[4][2];
#pragma unroll
            for (int nt = 0; nt < 4; nt++) {
                b[nt][0] = fbits(Bs[kb + tig    ][wn + nt * 8 + g]);
                b[nt][1] = fbits(Bs[kb + tig + 4][wn + nt * 8 + g]);
            }
#pragma unroll
            for (int mt = 0; mt < 4; mt++)
#pragma unroll
                for (int nt = 0; nt < 4; nt++)
                    mma8(acc[mt][nt], a[mt][0], a[mt][1], a[mt][2], a[mt][3],
                         b[nt][0], b[nt][1]);
        }
        __syncthreads();
    }

    // Epilogue: bias + store to [B][NH][S][HD]
#pragma unroll
    for (int mt = 0; mt < 4; mt++) {
        int r0 = row0 + wm + mt * 16 + g;
        int r1 = r0 + 8;
        int bb0 = r0 / SEQ, s0 = r0 % SEQ;
        int bb1 = r1 / SEQ, s1 = r1 % SEQ;
        float* p0 = dst + (((size_t)bb0 * NH + h) * SEQ + s0) * HD;
        float* p1 = dst + (((size_t)bb1 * NH + h) * SEQ + s1) * HD;
#pragma unroll
        for (int nt = 0; nt < 4; nt++) {
            int cc = wn + nt * 8 + 2 * tig;
            float b0 = bias[ncol + cc], b1 = bias[ncol + cc + 1];
            float2 o0 = {acc[mt][nt][0] + b0, acc[mt][nt][1] + b1};
            float2 o1 = {acc[mt][nt][2] + b0, acc[mt][nt][3] + b1};
            *(float2*)&p0[cc] = o0;
            *(float2*)&p1[cc] = o1;
        }
    }
}

// ---------------------------------------------------------------------------
// Kernel 2: flash attention, tf32 MMA. Br=64, Bc=32, 128 threads (4 warps),
// warp w owns q-rows [w*16, w*16+16). Softmax in C-fragment registers.
// ---------------------------------------------------------------------------
__global__ __launch_bounds__(128) void flash_attn(
    const float* __restrict__ mask, float* __restrict__ out)
{
    __shared__ float Qs[64][68];   // [q][d], A-pattern stride 68 (conflict-free)
    __shared__ float Ks[64][40];   // [d][s], B-pattern stride 40 (conflict-free)
    __shared__ float Vs[32][72];   // [s][d], B-pattern stride 72 (conflict-free)
    __shared__ float Ps[64][36];   // [q][s], A-pattern stride 36 (conflict-free)
    __shared__ float Ms[32];

    const int b  = blockIdx.z;
    const int h  = blockIdx.y;
    const int q0 = blockIdx.x * 64;

    const int tid  = threadIdx.x;
    const int warp = tid >> 5;
    const int lane = tid & 31;
    const int g    = lane >> 2;
    const int tig  = lane & 3;
    const int wq   = warp * 16;

    const float* Qg = g_q + ((size_t)(b * NH + h) * SEQ) * HD;
    const float* Kg = g_k + ((size_t)(b * NH + h) * SEQ) * HD;
    const float* Vg = g_v + ((size_t)(b * NH + h) * SEQ) * HD;
    const float* mk = mask + b * SEQ;

    // Load Q tile (64x64), tf32-converted
#pragma unroll
    for (int i = 0; i < 8; i++) {
        int lin = tid + i * 128;
        int r   = lin >> 4;
        int c4  = (lin & 15) * 4;
        float4 v = *(const float4*)&Qg[(size_t)(q0 + r) * HD + c4];
        Qs[r][c4 + 0] = f2tf(v.x); Qs[r][c4 + 1] = f2tf(v.y);
        Qs[r][c4 + 2] = f2tf(v.z); Qs[r][c4 + 3] = f2tf(v.w);
    }

    float o[8][4];
#pragma unroll
    for (int i = 0; i < 8; i++)
#pragma unroll
        for (int j = 0; j < 4; j++) o[i][j] = 0.f;
    float m0 = -1e30f, m1 = -1e30f, l0 = 0.f, l1 = 0.f;
    const float SCALE = 0.125f;   // 1/sqrt(64)

    for (int kc = 0; kc < SEQ; kc += 32) {
        __syncthreads();   // Ks/Vs consumers of previous iter done (also covers Qs stores)
#pragma unroll
        for (int i = 0; i < 4; i++) {
            int lin = tid + i * 128;
            int r   = lin >> 4;            // s 0..31
            int c4  = (lin & 15) * 4;      // d
            float4 kv = *(const float4*)&Kg[(size_t)(kc + r) * HD + c4];
            Ks[c4 + 0][r] = f2tf(kv.x); Ks[c4 + 1][r] = f2tf(kv.y);
            Ks[c4 + 2][r] = f2tf(kv.z); Ks[c4 + 3][r] = f2tf(kv.w);
            float4 vv = *(const float4*)&Vg[(size_t)(kc + r) * HD + c4];
            float4 vt = {f2tf(vv.x), f2tf(vv.y), f2tf(vv.z), f2tf(vv.w)};
            *(float4*)&Vs[r][c4] = vt;
        }
        if (tid < 32) Ms[tid] = mk[kc + tid];
        __syncthreads();

        // S = Q K^T  (16x32 per warp)
        float s_acc[4][4];
#pragma unroll
        for (int nt = 0; nt < 4; nt++)
#pragma unroll
            for (int j = 0; j < 4; j++) s_acc[nt][j] = 0.f;
#pragma unroll
        for (int kk = 0; kk < 8; kk++) {
            const int kb = kk * 8;
            unsigned a0 = fbits(Qs[wq + g    ][kb + tig    ]);
            unsigned a1 = fbits(Qs[wq + g + 8][kb + tig    ]);
            unsigned a2 = fbits(Qs[wq + g    ][kb + tig + 4]);
            unsigned a3 = fbits(Qs[wq + g + 8][kb + tig + 4]);
#pragma unroll
            for (int nt = 0; nt < 4; nt++) {
                unsigned b0 = fbits(Ks[kb + tig    ][nt * 8 + g]);
                unsigned b1 = fbits(Ks[kb + tig + 4][nt * 8 + g]);
                mma8(s_acc[nt], a0, a1, a2, a3, b0, b1);
            }
        }

        // scale + mask + row maxes (rows wq+g and wq+g+8)
        float rm0 = -1e30f, rm1 = -1e30f;
#pragma unroll
        for (int nt = 0; nt < 4; nt++) {
            float mv0 = Ms[nt * 8 + 2 * tig];
            float mv1 = Ms[nt * 8 + 2 * tig + 1];
            s_acc[nt][0] = s_acc[nt][0] * SCALE + mv0;
            s_acc[nt][1] = s_acc[nt][1] * SCALE + mv1;
            s_acc[nt][2] = s_acc[nt][2] * SCALE + mv0;
            s_acc[nt][3] = s_acc[nt][3] * SCALE + mv1;
            rm0 = fmaxf(rm0, fmaxf(s_acc[nt][0], s_acc[nt][1]));
            rm1 = fmaxf(rm1, fmaxf(s_acc[nt][2], s_acc[nt][3]));
        }
        rm0 = fmaxf(rm0, __shfl_xor_sync(0xffffffffu, rm0, 1));
        rm0 = fmaxf(rm0, __shfl_xor_sync(0xffffffffu, rm0, 2));
        rm1 = fmaxf(rm1, __shfl_xor_sync(0xffffffffu, rm1, 1));
        rm1 = fmaxf(rm1, __shfl_xor_sync(0xffffffffu, rm1, 2));

        float mn0 = fmaxf(m0, rm0), mn1 = fmaxf(m1, rm1);
        float al0 = __expf(m0 - mn0), al1 = __expf(m1 - mn1);
        m0 = mn0; m1 = mn1;

        float sum0 = 0.f, sum1 = 0.f;
#pragma unroll
        for (int nt = 0; nt < 4; nt++) {
            float p0 = __expf(s_acc[nt][0] - mn0);
            float p1 = __expf(s_acc[nt][1] - mn0);
            float p2 = __expf(s_acc[nt][2] - mn1);
            float p3 = __expf(s_acc[nt][3] - mn1);
            sum0 += p0 + p1; sum1 += p2 + p3;
            int col = nt * 8 + 2 * tig;
            float2 w0 = {f2tf(p0), f2tf(p1)};
            float2 w1 = {f2tf(p2), f2tf(p3)};
            *(float2*)&Ps[wq + g    ][col] = w0;
            *(float2*)&Ps[wq + g + 8][col] = w1;
        }
        sum0 += __shfl_xor_sync(0xffffffffu, sum0, 1);
        sum0 += __shfl_xor_sync(0xffffffffu, sum0, 2);
        sum1 += __shfl_xor_sync(0xffffffffu, sum1, 1);
        sum1 += __shfl_xor_sync(0xffffffffu, sum1, 2);
        l0 = l0 * al0 + sum0;
        l1 = l1 * al1 + sum1;

#pragma unroll
        for (int nt = 0; nt < 8; nt++) {
            o[nt][0] *= al0; o[nt][1] *= al0;
            o[nt][2] *= al1; o[nt][3] *= al1;
        }
        __syncwarp();   // Ps is warp-private (rows wq..wq+15)

        // O += P V   (16x64 per warp, k=32)
#pragma unroll
        for (int kk = 0; kk < 4; kk++) {
            const int kb = kk * 8;
            unsigned a0 = fbits(Ps[wq + g    ][kb + tig    ]);
            unsigned a1 = fbits(Ps[wq + g + 8][kb + tig    ]);
            unsigned a2 = fbits(Ps[wq + g    ][kb + tig + 4]);
            unsigned a3 = fbits(Ps[wq + g + 8][kb + tig + 4]);
#pragma unroll
            for (int nt = 0; nt < 8; nt++) {
                unsigned b0 = fbits(Vs[kb + tig    ][nt * 8 + g]);
                unsigned b1 = fbits(Vs[kb + tig + 4][nt * 8 + g]);
                mma8(o[nt], a0, a1, a2, a3, b0, b1);
            }
        }
    }

    // Normalize + write out[b][s][h*64 + d]
    float inv0 = 1.f / l0, inv1 = 1.f / l1;
    int r0 = q0 + wq + g, r1 = r0 + 8;
    float* p0 = out + ((size_t)(b * SEQ + r0)) * HID + h * HD;
    float* p1 = out + ((size_t)(b * SEQ + r1)) * HID + h * HD;
#pragma unroll
    for (int nt = 0; nt < 8; nt++) {
        int d = nt * 8 + 2 * tig;
        float2 v0 = {o[nt][0] * inv0, o[nt][1] * inv0};
        float2 v1 = {o[nt][2] * inv1, o[nt][3] * inv1};
        *(float2*)&p0[d] = v0;
        *(float2*)&p1[d] = v1;
    }
}

// ---------------------------------------------------------------------------
extern "C" void kernel_launch(void* const* d_in, const int* in_sizes, int n_in,
                              void* d_out, int out_size)
{
    const float* X    = (const float*)d_in[0];
    const float* mask = (const float*)d_in[1];
    const float* Wq   = (const float*)d_in[2];
    const float* bq   = (const float*)d_in[3];
    const float* Wk   = (const float*)d_in[4];
    const float* bk   = (const float*)d_in[5];
    const float* Wv   = (const float*)d_in[6];
    const float* bv   = (const float*)d_in[7];
    float* out = (float*)d_out;

    dim3 g1(48, 64);             // 48 col-tiles (3 mats x 16 heads), 8192/128 row tiles
    qkv_gemm<<<g1, 128>>>(X, Wq, bq, Wk, bk, Wv, bv);

    dim3 g2(32, NH, Bsz);        // 2048/64 q-tiles, heads, batch
    flash_attn<<<g2, 128>>>(mask, out);
}

// round 3
// speedup vs baseline: 5.0635x; 1.3904x over previous
#include <cuda_runtime.h>
#include <math.h>

#define Bsz 4
#define SEQ 2048
#define HID 1024
#define NH 16
#define HD 64

// Scratch Q,K,V in [B][NH][S][HD] layout.
__device__ float g_q[Bsz*NH*SEQ*HD];
__device__ float g_k[Bsz*NH*SEQ*HD];
__device__ float g_v[Bsz*NH*SEQ*HD];

// ---------------------------------------------------------------------------
__device__ __forceinline__ float f2tf(float x) {
    unsigned u;
    asm("cvt.rna.tf32.f32 %0, %1;" : "=r"(u) : "f"(x));
    return __uint_as_float(u);
}
__device__ __forceinline__ unsigned fbits(float x) { return __float_as_uint(x); }

__device__ __forceinline__ void mma8(float* c,
                                     unsigned a0, unsigned a1, unsigned a2, unsigned a3,
                                     unsigned b0, unsigned b1) {
    asm volatile(
        "mma.sync.aligned.m16n8k8.row.col.f32.tf32.tf32.f32 "
        "{%0,%1,%2,%3},{%4,%5,%6,%7},{%8,%9},{%0,%1,%2,%3};"
        : "+f"(c[0]), "+f"(c[1]), "+f"(c[2]), "+f"(c[3])
        : "r"(a0), "r"(a1), "r"(a2), "r"(a3), "r"(b0), "r"(b1));
}

// ---------------------------------------------------------------------------
// Kernel 1: fused QKV projection, tf32 MMA (unchanged from R2).
// ---------------------------------------------------------------------------
__global__ __launch_bounds__(128) void qkv_gemm(
    const float* __restrict__ X,
    const float* __restrict__ Wq, const float* __restrict__ bq,
    const float* __restrict__ Wk, const float* __restrict__ bk,
    const float* __restrict__ Wv, const float* __restrict__ bv)
{
    __shared__ float As[128][20];
    __shared__ float Bs[16][72];

    const int tid  = threadIdx.x;
    const int warp = tid >> 5;
    const int lane = tid & 31;
    const int g    = lane >> 2;
    const int tig  = lane & 3;

    const int row0   = blockIdx.y * 128;
    const int colblk = blockIdx.x;
    const int sel    = colblk >> 4;
    const int h      = colblk & 15;
    const int ncol   = h * 64;

    const float* W    = (sel == 0) ? Wq : (sel == 1) ? Wk : Wv;
    const float* bias = (sel == 0) ? bq : (sel == 1) ? bk : bv;
    float*       dst  = (sel == 0) ? g_q : (sel == 1) ? g_k : g_v;

    const int wm = (warp >> 1) * 64;
    const int wn = (warp & 1) * 32;

    float acc[4][4][4];
#pragma unroll
    for (int i = 0; i < 4; i++)
#pragma unroll
        for (int j = 0; j < 4; j++)
#pragma unroll
            for (int k = 0; k < 4; k++) acc[i][j][k] = 0.f;

    const int arow = tid >> 2;
    const int ac4  = (tid & 3) * 4;
    const int brow = tid >> 4;
    const int bc4  = (tid & 15) * 4;

    for (int k0 = 0; k0 < HID; k0 += 16) {
#pragma unroll
        for (int i = 0; i < 4; i++) {
            int r = arow + i * 32;
            float4 v = *(const float4*)&X[(size_t)(row0 + r) * HID + k0 + ac4];
            As[r][ac4 + 0] = f2tf(v.x); As[r][ac4 + 1] = f2tf(v.y);
            As[r][ac4 + 2] = f2tf(v.z); As[r][ac4 + 3] = f2tf(v.w);
        }
#pragma unroll
        for (int i = 0; i < 2; i++) {
            int r = brow + i * 8;
            float4 v = *(const float4*)&W[(size_t)(k0 + r) * HID + ncol + bc4];
            Bs[r][bc4 + 0] = f2tf(v.x); Bs[r][bc4 + 1] = f2tf(v.y);
            Bs[r][bc4 + 2] = f2tf(v.z); Bs[r][bc4 + 3] = f2tf(v.w);
        }
        __syncthreads();

#pragma unroll
        for (int ks = 0; ks < 2; ks++) {
            const int kb = ks * 8;
            unsigned a[4][4];
#pragma unroll
            for (int mt = 0; mt < 4; mt++) {
                int r = wm + mt * 16;
                a[mt][0] = fbits(As[r + g    ][kb + tig    ]);
                a[mt][1] = fbits(As[r + g + 8][kb + tig    ]);
                a[mt][2] = fbits(As[r + g    ][kb + tig + 4]);
                a[mt][3] = fbits(As[r + g + 8][kb + tig + 4]);
            }
            unsigned b[4][2];
#pragma unroll
            for (int nt = 0; nt < 4; nt++) {
                b[nt][0] = fbits(Bs[kb + tig    ][wn + nt * 8 + g]);
                b[nt][1] = fbits(Bs[kb + tig + 4][wn + nt * 8 + g]);
            }
#pragma unroll
            for (int mt = 0; mt < 4; mt++)
#pragma unroll
                for (int nt = 0; nt < 4; nt++)
                    mma8(acc[mt][nt], a[mt][0], a[mt][1], a[mt][2], a[mt][3],
                         b[nt][0], b[nt][1]);
        }
        __syncthreads();
    }

#pragma unroll
    for (int mt = 0; mt < 4; mt++) {
        int r0 = row0 + wm + mt * 16 + g;
        int r1 = r0 + 8;
        int bb0 = r0 / SEQ, s0 = r0 % SEQ;
        int bb1 = r1 / SEQ, s1 = r1 % SEQ;
        float* p0 = dst + (((size_t)bb0 * NH + h) * SEQ + s0) * HD;
        float* p1 = dst + (((size_t)bb1 * NH + h) * SEQ + s1) * HD;
#pragma unroll
        for (int nt = 0; nt < 4; nt++) {
            int cc = wn + nt * 8 + 2 * tig;
            float b0 = bias[ncol + cc], b1 = bias[ncol + cc + 1];
            float2 o0 = {acc[mt][nt][0] + b0, acc[mt][nt][1] + b1};
            float2 o1 = {acc[mt][nt][2] + b0, acc[mt][nt][3] + b1};
            *(float2*)&p0[cc] = o0;
            *(float2*)&p1[cc] = o1;
        }
    }
}

// ---------------------------------------------------------------------------
// Kernel 2: flash attention v2. Br=64, Bc=64, 128 threads = 4 warps in 2x2.
// Warp (wr,wc): S rows wr*32..+32, cols wc*32..+32. Split-k PV (k-half = wc),
// O partials in registers, combined once at the end. Ps overlays Ks.
// Smem layouts chosen conflict-free for all mma fragment access patterns:
//   Qs  [64][68]  (A: row*68 + k+tig     -> g*4+tig)
//   Ks  [64][68]  (B: col*68 + k+tig     -> g*4+tig)   [s][d], NO transpose
//   Ps  [64][68]  (A: row*68 + k+tig     -> g*4+tig)   overlays Ks
//   Vs  [64][72]  (B: (k+tig)*72 + col   -> tig*8+g)   [s][d]
// ---------------------------------------------------------------------------
#define SM_Q   0
#define SM_KP  4352
#define SM_V   8704
#define SM_MS  13312
#define SM_RM  13376
#define SM_RS  13504
#define SM_FLT 13632
#define SMEM_BYTES (SM_FLT * 4)

__global__ __launch_bounds__(128) void flash_attn(
    const float* __restrict__ mask, float* __restrict__ out)
{
    extern __shared__ float sm[];
    float* Qs  = sm + SM_Q;
    float* KPs = sm + SM_KP;
    float* Vs  = sm + SM_V;
    float* Ms  = sm + SM_MS;
    float* RM  = sm + SM_RM;
    float* RS  = sm + SM_RS;

    const int b  = blockIdx.z;
    const int h  = blockIdx.y;
    const int q0 = blockIdx.x * 64;

    const int tid  = threadIdx.x;
    const int warp = tid >> 5;
    const int lane = tid & 31;
    const int g    = lane >> 2;
    const int tig  = lane & 3;
    const int wr   = warp >> 1;
    const int wc   = warp & 1;
    const int qr   = wr * 32;        // this warp's q-row base
    const int scb  = wc * 32;        // this warp's key-col / k-half base

    const float* Qg = g_q + ((size_t)(b * NH + h) * SEQ) * HD;
    const float* Kg = g_k + ((size_t)(b * NH + h) * SEQ) * HD;
    const float* Vg = g_v + ((size_t)(b * NH + h) * SEQ) * HD;
    const float* mk = mask + b * SEQ;

    // Load Q tile 64x64 (tf32-converted), coalesced float4
#pragma unroll
    for (int i = 0; i < 8; i++) {
        int lin = tid + i * 128;
        int r   = lin >> 4;
        int c4  = (lin & 15) * 4;
        float4 v = *(const float4*)&Qg[(size_t)(q0 + r) * HD + c4];
        float4 t = {f2tf(v.x), f2tf(v.y), f2tf(v.z), f2tf(v.w)};
        *(float4*)&Qs[r * 68 + c4] = t;
    }

    float o[2][8][4];
#pragma unroll
    for (int mt = 0; mt < 2; mt++)
#pragma unroll
        for (int nt = 0; nt < 8; nt++)
#pragma unroll
            for (int j = 0; j < 4; j++) o[mt][nt][j] = 0.f;

    float mrow[2][2] = {{-1e30f, -1e30f}, {-1e30f, -1e30f}};
    float lrow[2][2] = {{0.f, 0.f}, {0.f, 0.f}};
    const float SCALE = 0.125f;

    for (int kc = 0; kc < SEQ; kc += 64) {
        __syncthreads();   // prev iter's PV done with Vs/Ps(=Ks region)
        // Load K,V tiles 64x64 each, [s][d], coalesced float4
#pragma unroll
        for (int i = 0; i < 8; i++) {
            int lin = tid + i * 128;
            int r   = lin >> 4;
            int c4  = (lin & 15) * 4;
            float4 kv = *(const float4*)&Kg[(size_t)(kc + r) * HD + c4];
            float4 kt = {f2tf(kv.x), f2tf(kv.y), f2tf(kv.z), f2tf(kv.w)};
            *(float4*)&KPs[r * 68 + c4] = kt;
            float4 vv = *(const float4*)&Vg[(size_t)(kc + r) * HD + c4];
            float4 vt = {f2tf(vv.x), f2tf(vv.y), f2tf(vv.z), f2tf(vv.w)};
            *(float4*)&Vs[r * 72 + c4] = vt;
        }
        if (tid < 64) Ms[tid] = mk[kc + tid];
        __syncthreads();

        // ---- S = Q K^T : 32x32 per warp (mt=2, nt=4) ----
        float s[2][4][4];
#pragma unroll
        for (int mt = 0; mt < 2; mt++)
#pragma unroll
            for (int nt = 0; nt < 4; nt++)
#pragma unroll
                for (int j = 0; j < 4; j++) s[mt][nt][j] = 0.f;

#pragma unroll
        for (int kk = 0; kk < 8; kk++) {
            const int kb = kk * 8;
            unsigned a[2][4];
#pragma unroll
            for (int mt = 0; mt < 2; mt++) {
                const float* rp = Qs + (qr + mt * 16) * 68;
                a[mt][0] = fbits(rp[(g    ) * 68 + kb + tig    ]);
                a[mt][1] = fbits(rp[(g + 8) * 68 + kb + tig    ]);
                a[mt][2] = fbits(rp[(g    ) * 68 + kb + tig + 4]);
                a[mt][3] = fbits(rp[(g + 8) * 68 + kb + tig + 4]);
            }
#pragma unroll
            for (int nt = 0; nt < 4; nt++) {
                const float* cp = KPs + (scb + nt * 8 + g) * 68;
                unsigned b0 = fbits(cp[kb + tig    ]);
                unsigned b1 = fbits(cp[kb + tig + 4]);
                mma8(s[0][nt], a[0][0], a[0][1], a[0][2], a[0][3], b0, b1);
                mma8(s[1][nt], a[1][0], a[1][1], a[1][2], a[1][3], b0, b1);
            }
        }

        // ---- scale + mask + partial row max (rows: qr+mt*16+g, +8) ----
        float rm[2][2] = {{-1e30f, -1e30f}, {-1e30f, -1e30f}};
#pragma unroll
        for (int mt = 0; mt < 2; mt++)
#pragma unroll
            for (int nt = 0; nt < 4; nt++) {
                int col = scb + nt * 8 + 2 * tig;
                float mv0 = Ms[col], mv1 = Ms[col + 1];
                s[mt][nt][0] = s[mt][nt][0] * SCALE + mv0;
                s[mt][nt][1] = s[mt][nt][1] * SCALE + mv1;
                s[mt][nt][2] = s[mt][nt][2] * SCALE + mv0;
                s[mt][nt][3] = s[mt][nt][3] * SCALE + mv1;
                rm[mt][0] = fmaxf(rm[mt][0], fmaxf(s[mt][nt][0], s[mt][nt][1]));
                rm[mt][1] = fmaxf(rm[mt][1], fmaxf(s[mt][nt][2], s[mt][nt][3]));
            }
#pragma unroll
        for (int mt = 0; mt < 2; mt++)
#pragma unroll
            for (int hh = 0; hh < 2; hh++) {
                rm[mt][hh] = fmaxf(rm[mt][hh], __shfl_xor_sync(0xffffffffu, rm[mt][hh], 1));
                rm[mt][hh] = fmaxf(rm[mt][hh], __shfl_xor_sync(0xffffffffu, rm[mt][hh], 2));
            }
        if (tig == 0) {
#pragma unroll
            for (int mt = 0; mt < 2; mt++) {
                RM[wc * 64 + qr + mt * 16 + g    ] = rm[mt][0];
                RM[wc * 64 + qr + mt * 16 + g + 8] = rm[mt][1];
            }
        }
        __syncthreads();

        // ---- combine maxes across col-halves, exp, write P (overlays Ks) ----
        float alpha[2][2];
#pragma unroll
        for (int mt = 0; mt < 2; mt++)
#pragma unroll
            for (int hh = 0; hh < 2; hh++) {
                int row = qr + mt * 16 + g + hh * 8;
                float mb = fmaxf(RM[row], RM[64 + row]);
                float mn = fmaxf(mrow[mt][hh], mb);
                alpha[mt][hh] = __expf(mrow[mt][hh] - mn);
                mrow[mt][hh] = mn;
            }

        float sum[2][2] = {{0.f, 0.f}, {0.f, 0.f}};
#pragma unroll
        for (int mt = 0; mt < 2; mt++)
#pragma unroll
            for (int nt = 0; nt < 4; nt++) {
                float p0 = __expf(s[mt][nt][0] - mrow[mt][0]);
                float p1 = __expf(s[mt][nt][1] - mrow[mt][0]);
                float p2 = __expf(s[mt][nt][2] - mrow[mt][1]);
                float p3 = __expf(s[mt][nt][3] - mrow[mt][1]);
                sum[mt][0] += p0 + p1;
                sum[mt][1] += p2 + p3;
                int col = scb + nt * 8 + 2 * tig;
                float2 w0 = {f2tf(p0), f2tf(p1)};
                float2 w1 = {f2tf(p2), f2tf(p3)};
                *(float2*)&KPs[(qr + mt * 16 + g    ) * 68 + col] = w0;
                *(float2*)&KPs[(qr + mt * 16 + g + 8) * 68 + col] = w1;
            }
#pragma unroll
        for (int mt = 0; mt < 2; mt++)
#pragma unroll
            for (int hh = 0; hh < 2; hh++) {
                sum[mt][hh] += __shfl_xor_sync(0xffffffffu, sum[mt][hh], 1);
                sum[mt][hh] += __shfl_xor_sync(0xffffffffu, sum[mt][hh], 2);
            }
        if (tig == 0) {
#pragma unroll
            for (int mt = 0; mt < 2; mt++) {
                RS[wc * 64 + qr + mt * 16 + g    ] = sum[mt][0];
                RS[wc * 64 + qr + mt * 16 + g + 8] = sum[mt][1];
            }
        }
        __syncthreads();

        // ---- l update + rescale O partials ----
#pragma unroll
        for (int mt = 0; mt < 2; mt++)
#pragma unroll
            for (int hh = 0; hh < 2; hh++) {
                int row = qr + mt * 16 + g + hh * 8;
                lrow[mt][hh] = lrow[mt][hh] * alpha[mt][hh] + RS[row] + RS[64 + row];
            }
#pragma unroll
        for (int mt = 0; mt < 2; mt++)
#pragma unroll
            for (int nt = 0; nt < 8; nt++) {
                o[mt][nt][0] *= alpha[mt][0];
                o[mt][nt][1] *= alpha[mt][0];
                o[mt][nt][2] *= alpha[mt][1];
                o[mt][nt][3] *= alpha[mt][1];
            }

        // ---- O += P V over this warp's k-half (kk=4 steps of 8) ----
#pragma unroll
        for (int kk = 0; kk < 4; kk++) {
            const int kbg = scb + kk * 8;
            unsigned a[2][4];
#pragma unroll
            for (int mt = 0; mt < 2; mt++) {
                const float* rp = KPs + (qr + mt * 16) * 68;
                a[mt][0] = fbits(rp[(g    ) * 68 + kbg + tig    ]);
                a[mt][1] = fbits(rp[(g + 8) * 68 + kbg + tig    ]);
                a[mt][2] = fbits(rp[(g    ) * 68 + kbg + tig + 4]);
                a[mt][3] = fbits(rp[(g + 8) * 68 + kbg + tig + 4]);
            }
#pragma unroll
            for (int nt = 0; nt < 8; nt++) {
                unsigned b0 = fbits(Vs[(kbg + tig    ) * 72 + nt * 8 + g]);
                unsigned b1 = fbits(Vs[(kbg + tig + 4) * 72 + nt * 8 + g]);
                mma8(o[0][nt], a[0][0], a[0][1], a[0][2], a[0][3], b0, b1);
                mma8(o[1][nt], a[1][0], a[1][1], a[1][2], a[1][3], b0, b1);
            }
        }
    }

    // ---- combine the two k-half O partials, normalize, write ----
    __syncthreads();
    if (wc == 1) {
#pragma unroll
        for (int mt = 0; mt < 2; mt++)
#pragma unroll
            for (int nt = 0; nt < 8; nt++) {
                int r0  = qr + mt * 16 + g;
                int col = nt * 8 + 2 * tig;
                float2 w0 = {o[mt][nt][0], o[mt][nt][1]};
                float2 w1 = {o[mt][nt][2], o[mt][nt][3]};
                *(float2*)&KPs[r0 * 68 + col] = w0;
                *(float2*)&KPs[(r0 + 8) * 68 + col] = w1;
            }
    }
    __syncthreads();
    if (wc == 0) {
#pragma unroll
        for (int mt = 0; mt < 2; mt++) {
            float inv0 = 1.f / lrow[mt][0];
            float inv1 = 1.f / lrow[mt][1];
            int r0 = qr + mt * 16 + g;
            float* p0 = out + ((size_t)(b * SEQ + q0 + r0    )) * HID + h * HD;
            float* p1 = out + ((size_t)(b * SEQ + q0 + r0 + 8)) * HID + h * HD;
#pragma unroll
            for (int nt = 0; nt < 8; nt++) {
                int col = nt * 8 + 2 * tig;
                float2 e0 = *(float2*)&KPs[r0 * 68 + col];
                float2 e1 = *(float2*)&KPs[(r0 + 8) * 68 + col];
                float2 v0 = {(o[mt][nt][0] + e0.x) * inv0, (o[mt][nt][1] + e0.y) * inv0};
                float2 v1 = {(o[mt][nt][2] + e1.x) * inv1, (o[mt][nt][3] + e1.y) * inv1};
                *(float2*)&p0[col] = v0;
                *(float2*)&p1[col] = v1;
            }
        }
    }
}

// ---------------------------------------------------------------------------
extern "C" void kernel_launch(void* const* d_in, const int* in_sizes, int n_in,
                              void* d_out, int out_size)
{
    const float* X    = (const float*)d_in[0];
    const float* mask = (const float*)d_in[1];
    const float* Wq   = (const float*)d_in[2];
    const float* bq   = (const float*)d_in[3];
    const float* Wk   = (const float*)d_in[4];
    const float* bk   = (const float*)d_in[5];
    const float* Wv   = (const float*)d_in[6];
    const float* bv   = (const float*)d_in[7];
    float* out = (float*)d_out;

    cudaFuncSetAttribute(flash_attn, cudaFuncAttributeMaxDynamicSharedMemorySize,
                         SMEM_BYTES);

    dim3 g1(48, 64);
    qkv_gemm<<<g1, 128>>>(X, Wq, bq, Wk, bk, Wv, bv);

    dim3 g2(32, NH, Bsz);
    flash_attn<<<g2, 128, SMEM_BYTES>>>(mask, out);
}

// round 4
// speedup vs baseline: 8.7135x; 1.7209x over previous
#include <cuda_runtime.h>
#include <cuda_fp16.h>
#include <math.h>
#include <stdint.h>

#define Bsz 4
#define SEQ 2048
#define HID 1024
#define NH 16
#define HD 64

// Scratch Q,K,V as fp16 in [B][NH][S][HD] layout.
__device__ __half g_q[Bsz*NH*SEQ*HD];
__device__ __half g_k[Bsz*NH*SEQ*HD];
__device__ __half g_v[Bsz*NH*SEQ*HD];

// ---------------------------------------------------------------------------
__device__ __forceinline__ uint32_t sptr(const void* p) {
    return (uint32_t)__cvta_generic_to_shared(p);
}
__device__ __forceinline__ void ldsm4(uint32_t* r, uint32_t a) {
    asm volatile("ldmatrix.sync.aligned.m8n8.x4.shared.b16 {%0,%1,%2,%3}, [%4];"
        : "=r"(r[0]), "=r"(r[1]), "=r"(r[2]), "=r"(r[3]) : "r"(a));
}
__device__ __forceinline__ void ldsm4t(uint32_t* r, uint32_t a) {
    asm volatile("ldmatrix.sync.aligned.m8n8.x4.trans.shared.b16 {%0,%1,%2,%3}, [%4];"
        : "=r"(r[0]), "=r"(r[1]), "=r"(r[2]), "=r"(r[3]) : "r"(a));
}
__device__ __forceinline__ void mma16(float* c, const uint32_t* a, const uint32_t* b) {
    asm volatile(
        "mma.sync.aligned.m16n8k16.row.col.f32.f16.f16.f32 "
        "{%0,%1,%2,%3},{%4,%5,%6,%7},{%8,%9},{%0,%1,%2,%3};"
        : "+f"(c[0]), "+f"(c[1]), "+f"(c[2]), "+f"(c[3])
        : "r"(a[0]), "r"(a[1]), "r"(a[2]), "r"(a[3]), "r"(b[0]), "r"(b[1]));
}
__device__ __forceinline__ __half2 f22h(float x, float y) {
    return __float22half2_rn(make_float2(x, y));
}

// ---------------------------------------------------------------------------
// Kernel 1: fused QKV projection, fp16 MMA + ldmatrix.
// Tile BM=128 x BN=128 (2 heads), BK=32. 256 threads = 8 warps (2m x 4n),
// warp tile 64x32 (mt=4, nt=4). blockIdx.x in [0,24): 8 col-tiles per matrix.
// As [128][40]h (80B stride, odd 16B units). Bs [32][136]h (272B stride, odd).
// A frag: ldmatrix x4 on [m][k]. B frag: ldmatrix x4 TRANS on [k][n].
// ---------------------------------------------------------------------------
__global__ __launch_bounds__(256) void qkv_gemm(
    const float* __restrict__ X,
    const float* __restrict__ Wq, const float* __restrict__ bq,
    const float* __restrict__ Wk, const float* __restrict__ bk,
    const float* __restrict__ Wv, const float* __restrict__ bv)
{
    __shared__ __half As[128][40];
    __shared__ __half Bs[32][136];

    const int tid  = threadIdx.x;
    const int warp = tid >> 5;
    const int lane = tid & 31;
    const int g    = lane >> 2;
    const int tig  = lane & 3;

    const int row0   = blockIdx.y * 128;
    const int colblk = blockIdx.x;           // 0..23
    const int sel    = colblk >> 3;          // 0=Q 1=K 2=V
    const int ncol   = (colblk & 7) * 128;

    const float* W    = (sel == 0) ? Wq : (sel == 1) ? Wk : Wv;
    const float* bias = (sel == 0) ? bq : (sel == 1) ? bk : bv;
    __half*      dst  = (sel == 0) ? g_q : (sel == 1) ? g_k : g_v;

    const int wm = (warp >> 2) * 64;    // 0/64
    const int wn = (warp & 3) * 32;     // 0/32/64/96

    float acc[4][4][4];
#pragma unroll
    for (int i = 0; i < 4; i++)
#pragma unroll
        for (int j = 0; j < 4; j++)
#pragma unroll
            for (int k = 0; k < 4; k++) acc[i][j][k] = 0.f;

    // ldmatrix lane-address components
    const int lrow = ((lane >> 3) & 1) * 8 + (lane & 7);
    const int lk8  = (lane >> 4) * 8;

    for (int k0 = 0; k0 < HID; k0 += 32) {
        // A: 128x32 floats -> half
#pragma unroll
        for (int i = 0; i < 4; i++) {
            int lin = tid + i * 256;
            int r   = lin >> 3;
            int c4  = (lin & 7) * 4;
            float4 v = *(const float4*)&X[(size_t)(row0 + r) * HID + k0 + c4];
            *(__half2*)&As[r][c4    ] = f22h(v.x, v.y);
            *(__half2*)&As[r][c4 + 2] = f22h(v.z, v.w);
        }
        // B: 32x128 floats -> half
#pragma unroll
        for (int i = 0; i < 4; i++) {
            int lin = tid + i * 256;
            int r   = lin >> 5;
            int c4  = (lin & 31) * 4;
            float4 v = *(const float4*)&W[(size_t)(k0 + r) * HID + ncol + c4];
            *(__half2*)&Bs[r][c4    ] = f22h(v.x, v.y);
            *(__half2*)&Bs[r][c4 + 2] = f22h(v.z, v.w);
        }
        __syncthreads();

#pragma unroll
        for (int ks = 0; ks < 2; ks++) {
            const int kb = ks * 16;
            uint32_t a[4][4];
#pragma unroll
            for (int mt = 0; mt < 4; mt++)
                ldsm4(a[mt], sptr(&As[wm + mt * 16 + lrow][kb + lk8]));
            uint32_t b[2][4];
#pragma unroll
            for (int nb = 0; nb < 2; nb++)
                ldsm4t(b[nb], sptr(&Bs[kb + lrow][wn + nb * 16 + lk8]));
#pragma unroll
            for (int mt = 0; mt < 4; mt++)
#pragma unroll
                for (int nt = 0; nt < 4; nt++)
                    mma16(acc[mt][nt], a[mt], &b[nt >> 1][(nt & 1) * 2]);
        }
        __syncthreads();
    }

    // Epilogue: bias + convert to half + store [B][NH][S][HD]
    const int bidx = row0 / SEQ;   // block-constant (128 | 2048)
#pragma unroll
    for (int mt = 0; mt < 4; mt++) {
        int r0 = row0 + wm + mt * 16 + g;
        int s0 = r0 & (SEQ - 1);
#pragma unroll
        for (int nt = 0; nt < 4; nt++) {
            int cc = wn + nt * 8 + 2 * tig;
            int h  = (ncol + cc) >> 6;
            int d  = (ncol + cc) & 63;
            float bf0 = bias[ncol + cc], bf1 = bias[ncol + cc + 1];
            __half* p = dst + (((size_t)bidx * NH + h) * SEQ + s0) * HD + d;
            *(__half2*)p               = f22h(acc[mt][nt][0] + bf0, acc[mt][nt][1] + bf1);
            *(__half2*)(p + 8 * HD)    = f22h(acc[mt][nt][2] + bf0, acc[mt][nt][3] + bf1);
        }
    }
}

// ---------------------------------------------------------------------------
// Kernel 2: flash attention, fp16 MMA + ldmatrix. Br=64, Bc=64, 128 threads
// = 4 warps in 2x2 (wr: rows, wc: col/k-half). Split-k PV with final combine.
// Smem (halves, stride 72 = 144B, odd 16B units -> conflict-free ldmatrix):
//   Qs [64][72] (A, non-trans)   Ks/Ps [64][72] ([s][d] B non-trans / A)
//   Vs [64][72] ([s][d], B TRANS)
// ---------------------------------------------------------------------------
__global__ __launch_bounds__(128) void flash_attn(
    const float* __restrict__ mask, float* __restrict__ out)
{
    __shared__ __align__(16) __half smh[3 * 64 * 72];
    __shared__ float smf[320];               // Ms 64 | RM 128 | RS 128
    __half* Qs  = smh;
    __half* KPs = smh + 64 * 72;
    __half* Vs  = smh + 2 * 64 * 72;
    float*  Ms  = smf;
    float*  RM  = smf + 64;
    float*  RS  = smf + 192;

    const int b  = blockIdx.z;
    const int h  = blockIdx.y;
    const int q0 = blockIdx.x * 64;

    const int tid  = threadIdx.x;
    const int warp = tid >> 5;
    const int lane = tid & 31;
    const int g    = lane >> 2;
    const int tig  = lane & 3;
    const int wr   = warp >> 1;
    const int wc   = warp & 1;
    const int qr   = wr * 32;
    const int scb  = wc * 32;

    const int lrow = ((lane >> 3) & 1) * 8 + (lane & 7);
    const int lk8  = (lane >> 4) * 8;

    const __half* Qg = g_q + ((size_t)(b * NH + h) * SEQ) * HD;
    const __half* Kg = g_k + ((size_t)(b * NH + h) * SEQ) * HD;
    const __half* Vg = g_v + ((size_t)(b * NH + h) * SEQ) * HD;
    const float*  mk = mask + b * SEQ;

    // Load Q tile 64x64 halves (16B chunks)
#pragma unroll
    for (int i = 0; i < 4; i++) {
        int lin = tid + i * 128;
        int r   = lin >> 3;
        int c8  = (lin & 7) * 8;
        *(uint4*)&Qs[r * 72 + c8] = *(const uint4*)&Qg[(size_t)(q0 + r) * HD + c8];
    }

    float o[2][8][4];
#pragma unroll
    for (int mt = 0; mt < 2; mt++)
#pragma unroll
        for (int nt = 0; nt < 8; nt++)
#pragma unroll
            for (int j = 0; j < 4; j++) o[mt][nt][j] = 0.f;

    float mrow[2][2] = {{-1e30f, -1e30f}, {-1e30f, -1e30f}};
    float lrowv[2][2] = {{0.f, 0.f}, {0.f, 0.f}};
    const float SCALE = 0.125f;

    for (int kc = 0; kc < SEQ; kc += 64) {
        __syncthreads();
#pragma unroll
        for (int i = 0; i < 4; i++) {
            int lin = tid + i * 128;
            int r   = lin >> 3;
            int c8  = (lin & 7) * 8;
            *(uint4*)&KPs[r * 72 + c8] = *(const uint4*)&Kg[(size_t)(kc + r) * HD + c8];
            *(uint4*)&Vs [r * 72 + c8] = *(const uint4*)&Vg[(size_t)(kc + r) * HD + c8];
        }
        if (tid < 64) Ms[tid] = mk[kc + tid];
        __syncthreads();

        // ---- S = Q K^T : 32x32 per warp ----
        float s[2][4][4];
#pragma unroll
        for (int mt = 0; mt < 2; mt++)
#pragma unroll
            for (int nt = 0; nt < 4; nt++)
#pragma unroll
                for (int j = 0; j < 4; j++) s[mt][nt][j] = 0.f;

#pragma unroll
        for (int kk = 0; kk < 4; kk++) {
            const int kb = kk * 16;
            uint32_t a[2][4];
#pragma unroll
            for (int mt = 0; mt < 2; mt++)
                ldsm4(a[mt], sptr(&Qs[(qr + mt * 16 + lrow) * 72 + kb + lk8]));
            uint32_t bm[2][4];
#pragma unroll
            for (int nb = 0; nb < 2; nb++)
                ldsm4(bm[nb], sptr(&KPs[(scb + nb * 16 + lk8 + (lane & 7)
                                        + ((lane >> 3) & 1) * 0) * 72
                                        + kb + ((lane >> 3) & 1) * 8]));
            // NOTE: B lane pattern: n = scb+nb*16 + (lane>>4)*8 + (lane&7),
            //       k = kb + ((lane>>3)&1)*8  -- rewrite explicitly:
#pragma unroll
            for (int mt = 0; mt < 2; mt++)
#pragma unroll
                for (int nt = 0; nt < 4; nt++)
                    mma16(s[mt][nt], a[mt], &bm[nt >> 1][(nt & 1) * 2]);
        }

        // ---- scale + mask + partial row max ----
        float rm[2][2] = {{-1e30f, -1e30f}, {-1e30f, -1e30f}};
#pragma unroll
        for (int mt = 0; mt < 2; mt++)
#pragma unroll
            for (int nt = 0; nt < 4; nt++) {
                int col = scb + nt * 8 + 2 * tig;
                float mv0 = Ms[col], mv1 = Ms[col + 1];
                s[mt][nt][0] = s[mt][nt][0] * SCALE + mv0;
                s[mt][nt][1] = s[mt][nt][1] * SCALE + mv1;
                s[mt][nt][2] = s[mt][nt][2] * SCALE + mv0;
                s[mt][nt][3] = s[mt][nt][3] * SCALE + mv1;
                rm[mt][0] = fmaxf(rm[mt][0], fmaxf(s[mt][nt][0], s[mt][nt][1]));
                rm[mt][1] = fmaxf(rm[mt][1], fmaxf(s[mt][nt][2], s[mt][nt][3]));
            }
#pragma unroll
        for (int mt = 0; mt < 2; mt++)
#pragma unroll
            for (int hh = 0; hh < 2; hh++) {
                rm[mt][hh] = fmaxf(rm[mt][hh], __shfl_xor_sync(0xffffffffu, rm[mt][hh], 1));
                rm[mt][hh] = fmaxf(rm[mt][hh], __shfl_xor_sync(0xffffffffu, rm[mt][hh], 2));
            }
        if (tig == 0) {
#pragma unroll
            for (int mt = 0; mt < 2; mt++) {
                RM[wc * 64 + qr + mt * 16 + g    ] = rm[mt][0];
                RM[wc * 64 + qr + mt * 16 + g + 8] = rm[mt][1];
            }
        }
        __syncthreads();

        // ---- combine maxes, exp, write P (half, overlays Ks) ----
        float alpha[2][2];
#pragma unroll
        for (int mt = 0; mt < 2; mt++)
#pragma unroll
            for (int hh = 0; hh < 2; hh++) {
                int row = qr + mt * 16 + g + hh * 8;
                float mb = fmaxf(RM[row], RM[64 + row]);
                float mn = fmaxf(mrow[mt][hh], mb);
                alpha[mt][hh] = __expf(mrow[mt][hh] - mn);
                mrow[mt][hh] = mn;
            }
        float sum[2][2] = {{0.f, 0.f}, {0.f, 0.f}};
#pragma unroll
        for (int mt = 0; mt < 2; mt++)
#pragma unroll
            for (int nt = 0; nt < 4; nt++) {
                float p0 = __expf(s[mt][nt][0] - mrow[mt][0]);
                float p1 = __expf(s[mt][nt][1] - mrow[mt][0]);
                float p2 = __expf(s[mt][nt][2] - mrow[mt][1]);
                float p3 = __expf(s[mt][nt][3] - mrow[mt][1]);
                sum[mt][0] += p0 + p1;
                sum[mt][1] += p2 + p3;
                int col = scb + nt * 8 + 2 * tig;
                *(__half2*)&KPs[(qr + mt * 16 + g    ) * 72 + col] = f22h(p0, p1);
                *(__half2*)&KPs[(qr + mt * 16 + g + 8) * 72 + col] = f22h(p2, p3);
            }
#pragma unroll
        for (int mt = 0; mt < 2; mt++)
#pragma unroll
            for (int hh = 0; hh < 2; hh++) {
                sum[mt][hh] += __shfl_xor_sync(0xffffffffu, sum[mt][hh], 1);
                sum[mt][hh] += __shfl_xor_sync(0xffffffffu, sum[mt][hh], 2);
            }
        if (tig == 0) {
#pragma unroll
            for (int mt = 0; mt < 2; mt++) {
                RS[wc * 64 + qr + mt * 16 + g    ] = sum[mt][0];
                RS[wc * 64 + qr + mt * 16 + g + 8] = sum[mt][1];
            }
        }
        __syncthreads();

        // ---- l update + rescale O ----
#pragma unroll
        for (int mt = 0; mt < 2; mt++)
#pragma unroll
            for (int hh = 0; hh < 2; hh++) {
                int row = qr + mt * 16 + g + hh * 8;
                lrowv[mt][hh] = lrowv[mt][hh] * alpha[mt][hh] + RS[row] + RS[64 + row];
            }
#pragma unroll
        for (int mt = 0; mt < 2; mt++)
#pragma unroll
            for (int nt = 0; nt < 8; nt++) {
                o[mt][nt][0] *= alpha[mt][0];
                o[mt][nt][1] *= alpha[mt][0];
                o[mt][nt][2] *= alpha[mt][1];
                o[mt][nt][3] *= alpha[mt][1];
            }

        // ---- O += P V over this warp's k-half ----
#pragma unroll
        for (int kk = 0; kk < 2; kk++) {
            const int kbg = scb + kk * 16;
            uint32_t a[2][4];
#pragma unroll
            for (int mt = 0; mt < 2; mt++)
                ldsm4(a[mt], sptr(&KPs[(qr + mt * 16 + lrow) * 72 + kbg + lk8]));
#pragma unroll
            for (int db = 0; db < 4; db++) {
                uint32_t bv[4];
                ldsm4t(bv, sptr(&Vs[(kbg + lrow) * 72 + db * 16 + lk8]));
                mma16(o[0][db * 2    ], a[0], &bv[0]);
                mma16(o[1][db * 2    ], a[1], &bv[0]);
                mma16(o[0][db * 2 + 1], a[0], &bv[2]);
                mma16(o[1][db * 2 + 1], a[1], &bv[2]);
            }
        }
    }

    // ---- combine k-half partials, normalize, write ----
    float* cb = (float*)smh;   // 64 x 68 f32 overlay on Qs+KPs (17.4KB < 18.4KB)
    __syncthreads();
    if (wc == 1) {
#pragma unroll
        for (int mt = 0; mt < 2; mt++)
#pragma unroll
            for (int nt = 0; nt < 8; nt++) {
                int r0  = qr + mt * 16 + g;
                int col = nt * 8 + 2 * tig;
                *(float2*)&cb[r0 * 68 + col]       = make_float2(o[mt][nt][0], o[mt][nt][1]);
                *(float2*)&cb[(r0 + 8) * 68 + col] = make_float2(o[mt][nt][2], o[mt][nt][3]);
            }
    }
    __syncthreads();
    if (wc == 0) {
#pragma unroll
        for (int mt = 0; mt < 2; mt++) {
            float inv0 = 1.f / lrowv[mt][0];
            float inv1 = 1.f / lrowv[mt][1];
            int r0 = qr + mt * 16 + g;
            float* p0 = out + ((size_t)(b * SEQ + q0 + r0    )) * HID + h * HD;
            float* p1 = out + ((size_t)(b * SEQ + q0 + r0 + 8)) * HID + h * HD;
#pragma unroll
            for (int nt = 0; nt < 8; nt++) {
                int col = nt * 8 + 2 * tig;
                float2 e0 = *(float2*)&cb[r0 * 68 + col];
                float2 e1 = *(float2*)&cb[(r0 + 8) * 68 + col];
                *(float2*)&p0[col] = make_float2((o[mt][nt][0] + e0.x) * inv0,
                                                 (o[mt][nt][1] + e0.y) * inv0);
                *(float2*)&p1[col] = make_float2((o[mt][nt][2] + e1.x) * inv1,
                                                 (o[mt][nt][3] + e1.y) * inv1);
            }
        }
    }
}

// ---------------------------------------------------------------------------
extern "C" void kernel_launch(void* const* d_in, const int* in_sizes, int n_in,
                              void* d_out, int out_size)
{
    const float* X    = (const float*)d_in[0];
    const float* mask = (const float*)d_in[1];
    const float* Wq   = (const float*)d_in[2];
    const float* bq   = (const float*)d_in[3];
    const float* Wk   = (const float*)d_in[4];
    const float* bk   = (const float*)d_in[5];
    const float* Wv   = (const float*)d_in[6];
    const float* bv   = (const float*)d_in[7];
    float* out = (float*)d_out;

    dim3 g1(24, 64);             // 24 col-tiles (3 mats x 8), 8192/128 row tiles
    qkv_gemm<<<g1, 256>>>(X, Wq, bq, Wk, bk, Wv, bv);

    dim3 g2(32, NH, Bsz);        // 2048/64 q-tiles, heads, batch
    flash_attn<<<g2, 128>>>(mask, out);
}

// round 8
// speedup vs baseline: 10.4500x; 1.1993x over previous
#include <cuda_runtime.h>
#include <cuda_fp16.h>
#include <math.h>
#include <stdint.h>

#define Bsz 4
#define SEQ 2048
#define HID 1024
#define NH 16
#define HD 64

// fp16 scratch
__device__ __half g_q[Bsz*NH*SEQ*HD];
__device__ __half g_k[Bsz*NH*SEQ*HD];
__device__ __half g_v[Bsz*NH*SEQ*HD];
__device__ __half g_xh[(size_t)Bsz*SEQ*HID];
__device__ __half g_wh[3*HID*HID];

// ---------------------------------------------------------------------------
__device__ __forceinline__ uint32_t sptr(const void* p) {
    return (uint32_t)__cvta_generic_to_shared(p);
}
__device__ __forceinline__ void ldsm4(uint32_t* r, uint32_t a) {
    asm volatile("ldmatrix.sync.aligned.m8n8.x4.shared.b16 {%0,%1,%2,%3}, [%4];"
        : "=r"(r[0]), "=r"(r[1]), "=r"(r[2]), "=r"(r[3]) : "r"(a));
}
__device__ __forceinline__ void ldsm4t(uint32_t* r, uint32_t a) {
    asm volatile("ldmatrix.sync.aligned.m8n8.x4.trans.shared.b16 {%0,%1,%2,%3}, [%4];"
        : "=r"(r[0]), "=r"(r[1]), "=r"(r[2]), "=r"(r[3]) : "r"(a));
}
__device__ __forceinline__ void mma16(float* c, const uint32_t* a, const uint32_t* b) {
    asm volatile(
        "mma.sync.aligned.m16n8k16.row.col.f32.f16.f16.f32 "
        "{%0,%1,%2,%3},{%4,%5,%6,%7},{%8,%9},{%0,%1,%2,%3};"
        : "+f"(c[0]), "+f"(c[1]), "+f"(c[2]), "+f"(c[3])
        : "r"(a[0]), "r"(a[1]), "r"(a[2]), "r"(a[3]), "r"(b[0]), "r"(b[1]));
}
__device__ __forceinline__ __half2 f22h(float x, float y) {
    return __float22half2_rn(make_float2(x, y));
}
__device__ __forceinline__ float ex2(float x) {
    float r; asm("ex2.approx.f32 %0, %1;" : "=f"(r) : "f"(x)); return r;
}
__device__ __forceinline__ void cpa16(uint32_t d, const void* s) {
    asm volatile("cp.async.cg.shared.global [%0], [%1], 16;" :: "r"(d), "l"(s));
}
__device__ __forceinline__ void cpa4(uint32_t d, const void* s) {
    asm volatile("cp.async.ca.shared.global [%0], [%1], 4;" :: "r"(d), "l"(s));
}
#define CP_COMMIT() asm volatile("cp.async.commit_group;")
#define CP_WAIT0()  asm volatile("cp.async.wait_group 0;")

// ---------------------------------------------------------------------------
// Kernel 0: convert X, Wq, Wk, Wv to fp16 scratch.
// ---------------------------------------------------------------------------
__global__ __launch_bounds__(256) void to_half(
    const float* __restrict__ X, const float* __restrict__ Wq,
    const float* __restrict__ Wk, const float* __restrict__ Wv)
{
    const int XG = (Bsz*SEQ*HID) / 4;
    const int WG = (HID*HID) / 4;
    int idx = blockIdx.x * blockDim.x + threadIdx.x;
    const float4* src;
    __half* dst;
    if (idx < XG)             { src = (const float4*)X  + idx;               dst = g_xh + (size_t)idx * 4; }
    else if (idx < XG + WG)   { src = (const float4*)Wq + (idx - XG);        dst = g_wh + (size_t)(idx - XG) * 4; }
    else if (idx < XG + 2*WG) { src = (const float4*)Wk + (idx - XG - WG);   dst = g_wh + (size_t)HID*HID + (size_t)(idx - XG - WG) * 4; }
    else if (idx < XG + 3*WG) { src = (const float4*)Wv + (idx - XG - 2*WG); dst = g_wh + (size_t)2*HID*HID + (size_t)(idx - XG - 2*WG) * 4; }
    else return;
    float4 v = *src;
    __half2 lo = f22h(v.x, v.y), hi = f22h(v.z, v.w);
    uint2 pack;
    pack.x = *(uint32_t*)&lo;
    pack.y = *(uint32_t*)&hi;
    *(uint2*)dst = pack;
}

// ---------------------------------------------------------------------------
// Kernel 1: fused QKV projection, fp16 in/out, BM=256 x BN=128, BK=32,
// 512 threads = 16 warps (4m x 4n), warp tile 64x32.
// ---------------------------------------------------------------------------
__global__ __launch_bounds__(512) void qkv_gemm(
    const float* __restrict__ bq, const float* __restrict__ bk,
    const float* __restrict__ bv)
{
    __shared__ __half As[256][40];
    __shared__ __half Bs[32][136];

    const int tid  = threadIdx.x;
    const int warp = tid >> 5;
    const int lane = tid & 31;
    const int g    = lane >> 2;
    const int tig  = lane & 3;

    const int row0   = blockIdx.y * 256;
    const int colblk = blockIdx.x;           // 0..23
    const int sel    = colblk >> 3;          // 0=Q 1=K 2=V
    const int ncol   = (colblk & 7) * 128;

    const __half* Wh  = g_wh + (size_t)sel * HID * HID;
    const float* bias = (sel == 0) ? bq : (sel == 1) ? bk : bv;
    __half*      dst  = (sel == 0) ? g_q : (sel == 1) ? g_k : g_v;

    const int wm = (warp >> 2) * 64;
    const int wn = (warp & 3) * 32;

    float acc[4][4][4];
#pragma unroll
    for (int i = 0; i < 4; i++)
#pragma unroll
        for (int j = 0; j < 4; j++)
#pragma unroll
            for (int k = 0; k < 4; k++) acc[i][j][k] = 0.f;

    const int lrow = ((lane >> 3) & 1) * 8 + (lane & 7);
    const int lk8  = (lane >> 4) * 8;

    for (int k0 = 0; k0 < HID; k0 += 32) {
#pragma unroll
        for (int i = 0; i < 2; i++) {
            int lin = tid + i * 512;
            int r   = lin >> 2;
            int c8  = (lin & 3) * 8;
            *(uint4*)&As[r][c8] =
                *(const uint4*)&g_xh[(size_t)(row0 + r) * HID + k0 + c8];
        }
        {
            int r  = tid >> 4;
            int c8 = (tid & 15) * 8;
            *(uint4*)&Bs[r][c8] =
                *(const uint4*)&Wh[(size_t)(k0 + r) * HID + ncol + c8];
        }
        __syncthreads();

#pragma unroll
        for (int ks = 0; ks < 2; ks++) {
            const int kb = ks * 16;
            uint32_t a[4][4];
#pragma unroll
            for (int mt = 0; mt < 4; mt++)
                ldsm4(a[mt], sptr(&As[wm + mt * 16 + lrow][kb + lk8]));
            uint32_t b[2][4];
#pragma unroll
            for (int nb = 0; nb < 2; nb++)
                ldsm4t(b[nb], sptr(&Bs[kb + lrow][wn + nb * 16 + lk8]));
#pragma unroll
            for (int mt = 0; mt < 4; mt++)
#pragma unroll
                for (int nt = 0; nt < 4; nt++)
                    mma16(acc[mt][nt], a[mt], &b[nt >> 1][(nt & 1) * 2]);
        }
        __syncthreads();
    }

    const int bidx = row0 >> 11;   // row0 / SEQ
#pragma unroll
    for (int mt = 0; mt < 4; mt++) {
        int r0 = row0 + wm + mt * 16 + g;
        int s0 = r0 & (SEQ - 1);
#pragma unroll
        for (int nt = 0; nt < 4; nt++) {
            int cc = wn + nt * 8 + 2 * tig;
            int h  = (ncol + cc) >> 6;
            int d  = (ncol + cc) & 63;
            float bf0 = bias[ncol + cc], bf1 = bias[ncol + cc + 1];
            __half* p = dst + (((size_t)bidx * NH + h) * SEQ + s0) * HD + d;
            *(__half2*)p            = f22h(acc[mt][nt][0] + bf0, acc[mt][nt][1] + bf1);
            *(__half2*)(p + 8 * HD) = f22h(acc[mt][nt][2] + bf0, acc[mt][nt][3] + bf1);
        }
    }
}

// ---------------------------------------------------------------------------
// Kernel 2: flash attention. Br=64, Bc=64, 128 threads, 4 warps (2 row x 2 col).
// Split-d PV: warp (wr,wc) computes S[32x32] at (qr,scb), PV over full k=64
// for d-slice [wc*32, wc*32+32). cp.async double-buffered K/V/mask pipeline.
// exp2-domain softmax. Dynamic smem:
//   Qs 64x72h | Kb 2x64x72h | Vb 2x64x72h | Ps 64x72h | Ms 2x64f | RM 128f | RS 128f
// ---------------------------------------------------------------------------
#define FA_SMEM (4608*2*6 + (128 + 128 + 128) * 4)

__global__ __launch_bounds__(128, 4) void flash_attn(
    const float* __restrict__ mask, float* __restrict__ out)
{
    extern __shared__ __align__(16) __half dsm[];
    float*  Ms = (float*)(dsm + 4608 * 6);      // after 6 half-tiles
    float*  RM = Ms + 128;
    float*  RS = RM + 128;
    const uint32_t sb  = sptr(dsm);
    const uint32_t KbB = sb + 9216;             // 2 buffers of 9216B
    const uint32_t VbB = sb + 27648;
    const uint32_t PsB = sb + 46080;
    const uint32_t MsB = sb + 55296;

    const int b  = blockIdx.z;
    const int h  = blockIdx.y;
    const int q0 = blockIdx.x * 64;

    const int tid  = threadIdx.x;
    const int warp = tid >> 5;
    const int lane = tid & 31;
    const int g    = lane >> 2;
    const int tig  = lane & 3;
    const int wr   = warp >> 1;
    const int wc   = warp & 1;
    const int qr   = wr * 32;
    const int scb  = wc * 32;

    const int lrow = ((lane >> 3) & 1) * 8 + (lane & 7);
    const int lk8  = (lane >> 4) * 8;
    const int bn   = (lane >> 4) * 8 + (lane & 7);
    const int bk8  = ((lane >> 3) & 1) * 8;

    const __half* Qg = g_q + ((size_t)(b * NH + h) * SEQ) * HD;
    const __half* Kg = g_k + ((size_t)(b * NH + h) * SEQ) * HD;
    const __half* Vg = g_v + ((size_t)(b * NH + h) * SEQ) * HD;
    const float*  mk = mask + b * SEQ;

    // Prologue: one async group = Q + K0 + V0 + M0
#pragma unroll
    for (int i = 0; i < 4; i++) {
        int lin = tid + i * 128;
        int r   = lin >> 3;
        int c8  = (lin & 7) * 8;
        uint32_t so = (uint32_t)(r * 72 + c8) * 2;
        cpa16(sb  + so, &Qg[(size_t)(q0 + r) * HD + c8]);
        cpa16(KbB + so, &Kg[(size_t)r * HD + c8]);
        cpa16(VbB + so, &Vg[(size_t)r * HD + c8]);
    }
    if (tid < 64) cpa4(MsB + tid * 4, &mk[tid]);
    CP_COMMIT();

    float o[2][4][4];
#pragma unroll
    for (int mt = 0; mt < 2; mt++)
#pragma unroll
        for (int nt = 0; nt < 4; nt++)
#pragma unroll
            for (int j = 0; j < 4; j++) o[mt][nt][j] = 0.f;

    float mrow[2][2] = {{-1e30f, -1e30f}, {-1e30f, -1e30f}};
    float lrowv[2][2] = {{0.f, 0.f}, {0.f, 0.f}};
    const float C1  = 0.18033688011112042f;     // 0.125 * log2(e)
    const float L2E = 1.4426950408889634f;

    for (int it = 0; it < 32; it++) {
        const int buf = it & 1;
        CP_WAIT0();
        __syncthreads();
        if (it < 31) {
            const int nb = buf ^ 1;
            const int kc = (it + 1) * 64;
#pragma unroll
            for (int i = 0; i < 4; i++) {
                int lin = tid + i * 128;
                int r   = lin >> 3;
                int c8  = (lin & 7) * 8;
                uint32_t so = (uint32_t)(nb * 9216 + (r * 72 + c8) * 2);
                cpa16(KbB + so, &Kg[(size_t)(kc + r) * HD + c8]);
                cpa16(VbB + so, &Vg[(size_t)(kc + r) * HD + c8]);
            }
            if (tid < 64) cpa4(MsB + (nb * 64 + tid) * 4, &mk[kc + tid]);
            CP_COMMIT();
        }
        const uint32_t Ku = KbB + buf * 9216;
        const uint32_t Vu = VbB + buf * 9216;
        const float* Mb = Ms + buf * 64;

        // ---- S = Q K^T : 32x32 per warp ----
        float s[2][4][4];
#pragma unroll
        for (int mt = 0; mt < 2; mt++)
#pragma unroll
            for (int nt = 0; nt < 4; nt++)
#pragma unroll
                for (int j = 0; j < 4; j++) s[mt][nt][j] = 0.f;

#pragma unroll
        for (int kk = 0; kk < 4; kk++) {
            const int kb = kk * 16;
            uint32_t a[2][4];
            ldsm4(a[0], sb + (uint32_t)((qr      + lrow) * 72 + kb + lk8) * 2);
            ldsm4(a[1], sb + (uint32_t)((qr + 16 + lrow) * 72 + kb + lk8) * 2);
            uint32_t bm[2][4];
            ldsm4(bm[0], Ku + (uint32_t)((scb      + bn) * 72 + kb + bk8) * 2);
            ldsm4(bm[1], Ku + (uint32_t)((scb + 16 + bn) * 72 + kb + bk8) * 2);
#pragma unroll
            for (int mt = 0; mt < 2; mt++)
#pragma unroll
                for (int nt = 0; nt < 4; nt++)
                    mma16(s[mt][nt], a[mt], &bm[nt >> 1][(nt & 1) * 2]);
        }

        // ---- exp2-domain scale + mask + partial row max ----
        float rm[2][2] = {{-1e30f, -1e30f}, {-1e30f, -1e30f}};
#pragma unroll
        for (int mt = 0; mt < 2; mt++)
#pragma unroll
            for (int nt = 0; nt < 4; nt++) {
                int col = scb + nt * 8 + 2 * tig;
                float mv0 = Mb[col] * L2E, mv1 = Mb[col + 1] * L2E;
                s[mt][nt][0] = s[mt][nt][0] * C1 + mv0;
                s[mt][nt][1] = s[mt][nt][1] * C1 + mv1;
                s[mt][nt][2] = s[mt][nt][2] * C1 + mv0;
                s[mt][nt][3] = s[mt][nt][3] * C1 + mv1;
                rm[mt][0] = fmaxf(rm[mt][0], fmaxf(s[mt][nt][0], s[mt][nt][1]));
                rm[mt][1] = fmaxf(rm[mt][1], fmaxf(s[mt][nt][2], s[mt][nt][3]));
            }
#pragma unroll
        for (int mt = 0; mt < 2; mt++)
#pragma unroll
            for (int hh = 0; hh < 2; hh++) {
                rm[mt][hh] = fmaxf(rm[mt][hh], __shfl_xor_sync(0xffffffffu, rm[mt][hh], 1));
                rm[mt][hh] = fmaxf(rm[mt][hh], __shfl_xor_sync(0xffffffffu, rm[mt][hh], 2));
            }
        if (tig == 0) {
#pragma unroll
            for (int mt = 0; mt < 2; mt++) {
                RM[wc * 64 + qr + mt * 16 + g    ] = rm[mt][0];
                RM[wc * 64 + qr + mt * 16 + g + 8] = rm[mt][1];
            }
        }
        __syncthreads();

        // ---- combine maxes, exp2, write P ----
        float alpha[2][2];
#pragma unroll
        for (int mt = 0; mt < 2; mt++)
#pragma unroll
            for (int hh = 0; hh < 2; hh++) {
                int row = qr + mt * 16 + g + hh * 8;
                float mb = fmaxf(RM[row], RM[64 + row]);
                float mn = fmaxf(mrow[mt][hh], mb);
                alpha[mt][hh] = ex2(mrow[mt][hh] - mn);
                mrow[mt][hh] = mn;
            }
        float sum[2][2] = {{0.f, 0.f}, {0.f, 0.f}};
        __half* Ph = dsm + (PsB - sb) / 2;
#pragma unroll
        for (int mt = 0; mt < 2; mt++)
#pragma unroll
            for (int nt = 0; nt < 4; nt++) {
                float p0 = ex2(s[mt][nt][0] - mrow[mt][0]);
                float p1 = ex2(s[mt][nt][1] - mrow[mt][0]);
                float p2 = ex2(s[mt][nt][2] - mrow[mt][1]);
                float p3 = ex2(s[mt][nt][3] - mrow[mt][1]);
                sum[mt][0] += p0 + p1;
                sum[mt][1] += p2 + p3;
                int col = scb + nt * 8 + 2 * tig;
                *(__half2*)&Ph[(qr + mt * 16 + g    ) * 72 + col] = f22h(p0, p1);
                *(__half2*)&Ph[(qr + mt * 16 + g + 8) * 72 + col] = f22h(p2, p3);
            }
#pragma unroll
        for (int mt = 0; mt < 2; mt++)
#pragma unroll
            for (int hh = 0; hh < 2; hh++) {
                sum[mt][hh] += __shfl_xor_sync(0xffffffffu, sum[mt][hh], 1);
                sum[mt][hh] += __shfl_xor_sync(0xffffffffu, sum[mt][hh], 2);
            }
        if (tig == 0) {
#pragma unroll
            for (int mt = 0; mt < 2; mt++) {
                RS[wc * 64 + qr + mt * 16 + g    ] = sum[mt][0];
                RS[wc * 64 + qr + mt * 16 + g + 8] = sum[mt][1];
            }
        }
        __syncthreads();

        // ---- l update + O rescale ----
#pragma unroll
        for (int mt = 0; mt < 2; mt++)
#pragma unroll
            for (int hh = 0; hh < 2; hh++) {
                int row = qr + mt * 16 + g + hh * 8;
                lrowv[mt][hh] = lrowv[mt][hh] * alpha[mt][hh] + RS[row] + RS[64 + row];
            }
#pragma unroll
        for (int mt = 0; mt < 2; mt++)
#pragma unroll
            for (int nt = 0; nt < 4; nt++) {
                o[mt][nt][0] *= alpha[mt][0];
                o[mt][nt][1] *= alpha[mt][0];
                o[mt][nt][2] *= alpha[mt][1];
                o[mt][nt][3] *= alpha[mt][1];
            }

        // ---- O += P V : full k=64, d-slice [wc*32, wc*32+32) ----
#pragma unroll
        for (int kk = 0; kk < 4; kk++) {
            const int kb = kk * 16;
            uint32_t a[2][4];
            ldsm4(a[0], PsB + (uint32_t)((qr      + lrow) * 72 + kb + lk8) * 2);
            ldsm4(a[1], PsB + (uint32_t)((qr + 16 + lrow) * 72 + kb + lk8) * 2);
#pragma unroll
            for (int db = 0; db < 2; db++) {
                uint32_t bv4[4];
                ldsm4t(bv4, Vu + (uint32_t)((kb + lrow) * 72 + wc * 32 + db * 16 + lk8) * 2);
                mma16(o[0][db * 2    ], a[0], &bv4[0]);
                mma16(o[1][db * 2    ], a[1], &bv4[0]);
                mma16(o[0][db * 2 + 1], a[0], &bv4[2]);
                mma16(o[1][db * 2 + 1], a[1], &bv4[2]);
            }
        }
    }

    // ---- normalize + direct store (warp owns its d-slice; no combine) ----
#pragma unroll
    for (int mt = 0; mt < 2; mt++) {
        float inv0 = 1.f / lrowv[mt][0];
        float inv1 = 1.f / lrowv[mt][1];
        int r0 = q0 + qr + mt * 16 + g;
        float* p0 = out + ((size_t)(b * SEQ + r0    )) * HID + h * HD + wc * 32;
        float* p1 = out + ((size_t)(b * SEQ + r0 + 8)) * HID + h * HD + wc * 32;
#pragma unroll
        for (int nt = 0; nt < 4; nt++) {
            int col = nt * 8 + 2 * tig;
            *(float2*)&p0[col] = make_float2(o[mt][nt][0] * inv0, o[mt][nt][1] * inv0);
            *(float2*)&p1[col] = make_float2(o[mt][nt][2] * inv1, o[mt][nt][3] * inv1);
        }
    }
}

// ---------------------------------------------------------------------------
extern "C" void kernel_launch(void* const* d_in, const int* in_sizes, int n_in,
                              void* d_out, int out_size)
{
    const float* X    = (const float*)d_in[0];
    const float* mask = (const float*)d_in[1];
    const float* Wq   = (const float*)d_in[2];
    const float* bq   = (const float*)d_in[3];
    const float* Wk   = (const float*)d_in[4];
    const float* bk   = (const float*)d_in[5];
    const float* Wv   = (const float*)d_in[6];
    const float* bv   = (const float*)d_in[7];
    float* out = (float*)d_out;

    cudaFuncSetAttribute(flash_attn, cudaFuncAttributeMaxDynamicSharedMemorySize,
                         FA_SMEM);

    const int XG = (Bsz*SEQ*HID) / 4;
    const int WG = (HID*HID) / 4;
    int cvt_blocks = (XG + 3 * WG + 255) / 256;
    to_half<<<cvt_blocks, 256>>>(X, Wq, Wk, Wv);

    dim3 g1(24, 32);             // 24 col-tiles (3 x 8), 8192/256 row tiles
    qkv_gemm<<<g1, 512>>>(bq, bk, bv);

    dim3 g2(32, NH, Bsz);
    flash_attn<<<g2, 128, FA_SMEM>>>(mask, out);
}

// round 10
// speedup vs baseline: 10.8401x; 1.0373x over previous
#include <cuda_runtime.h>
#include <cuda_fp16.h>
#include <math.h>
#include <stdint.h>

#define Bsz 4
#define SEQ 2048
#define HID 1024
#define NH 16
#define HD 64

// fp16 scratch
__device__ __half g_q[Bsz*NH*SEQ*HD];
__device__ __half g_k[Bsz*NH*SEQ*HD];
__device__ __half g_v[Bsz*NH*SEQ*HD];
__device__ __half g_xh[(size_t)Bsz*SEQ*HID];
__device__ __half g_wh[3*HID*HID];

// ---------------------------------------------------------------------------
__device__ __forceinline__ uint32_t sptr(const void* p) {
    return (uint32_t)__cvta_generic_to_shared(p);
}
__device__ __forceinline__ void ldsm4(uint32_t* r, uint32_t a) {
    asm volatile("ldmatrix.sync.aligned.m8n8.x4.shared.b16 {%0,%1,%2,%3}, [%4];"
        : "=r"(r[0]), "=r"(r[1]), "=r"(r[2]), "=r"(r[3]) : "r"(a));
}
__device__ __forceinline__ void ldsm4t(uint32_t* r, uint32_t a) {
    asm volatile("ldmatrix.sync.aligned.m8n8.x4.trans.shared.b16 {%0,%1,%2,%3}, [%4];"
        : "=r"(r[0]), "=r"(r[1]), "=r"(r[2]), "=r"(r[3]) : "r"(a));
}
__device__ __forceinline__ void mma16(float* c, const uint32_t* a, const uint32_t* b) {
    asm volatile(
        "mma.sync.aligned.m16n8k16.row.col.f32.f16.f16.f32 "
        "{%0,%1,%2,%3},{%4,%5,%6,%7},{%8,%9},{%0,%1,%2,%3};"
        : "+f"(c[0]), "+f"(c[1]), "+f"(c[2]), "+f"(c[3])
        : "r"(a[0]), "r"(a[1]), "r"(a[2]), "r"(a[3]), "r"(b[0]), "r"(b[1]));
}
__device__ __forceinline__ __half2 f22h(float x, float y) {
    return __float22half2_rn(make_float2(x, y));
}
__device__ __forceinline__ uint32_t f22hu(float x, float y) {
    __half2 h = __float22half2_rn(make_float2(x, y));
    return *(uint32_t*)&h;
}
__device__ __forceinline__ float ex2(float x) {
    float r; asm("ex2.approx.f32 %0, %1;" : "=f"(r) : "f"(x)); return r;
}
__device__ __forceinline__ void cpa16(uint32_t d, const void* s) {
    asm volatile("cp.async.cg.shared.global [%0], [%1], 16;" :: "r"(d), "l"(s));
}
__device__ __forceinline__ void cpa4(uint32_t d, const void* s) {
    asm volatile("cp.async.ca.shared.global [%0], [%1], 4;" :: "r"(d), "l"(s));
}
#define CP_COMMIT() asm volatile("cp.async.commit_group;")
#define CP_WAIT0()  asm volatile("cp.async.wait_group 0;")

// ---------------------------------------------------------------------------
// Kernel 0: convert X, Wq, Wk, Wv to fp16 scratch.
// ---------------------------------------------------------------------------
__global__ __launch_bounds__(256) void to_half(
    const float* __restrict__ X, const float* __restrict__ Wq,
    const float* __restrict__ Wk, const float* __restrict__ Wv)
{
    const int XG = (Bsz*SEQ*HID) / 4;
    const int WG = (HID*HID) / 4;
    int idx = blockIdx.x * blockDim.x + threadIdx.x;
    const float4* src;
    __half* dst;
    if (idx < XG)             { src = (const float4*)X  + idx;               dst = g_xh + (size_t)idx * 4; }
    else if (idx < XG + WG)   { src = (const float4*)Wq + (idx - XG);        dst = g_wh + (size_t)(idx - XG) * 4; }
    else if (idx < XG + 2*WG) { src = (const float4*)Wk + (idx - XG - WG);   dst = g_wh + (size_t)HID*HID + (size_t)(idx - XG - WG) * 4; }
    else if (idx < XG + 3*WG) { src = (const float4*)Wv + (idx - XG - 2*WG); dst = g_wh + (size_t)2*HID*HID + (size_t)(idx - XG - 2*WG) * 4; }
    else return;
    float4 v = *src;
    __half2 lo = f22h(v.x, v.y), hi = f22h(v.z, v.w);
    uint2 pack;
    pack.x = *(uint32_t*)&lo;
    pack.y = *(uint32_t*)&hi;
    *(uint2*)dst = pack;
}

// ---------------------------------------------------------------------------
// Kernel 1: fused QKV projection, fp16, BM=256 x BN=128, BK=32, 512 threads,
// cp.async double-buffered K-loop. Dynamic smem:
//   As 2 x 256x40h (20480B each) | Bs 2 x 32x136h (8704B each) = 58368B
// ---------------------------------------------------------------------------
#define QKV_SMEM 58368

__global__ __launch_bounds__(512) void qkv_gemm(
    const float* __restrict__ bq, const float* __restrict__ bk,
    const float* __restrict__ bv)
{
    extern __shared__ __align__(16) __half qsm[];
    const uint32_t qb = sptr(qsm);

    const int tid  = threadIdx.x;
    const int warp = tid >> 5;
    const int lane = tid & 31;
    const int g    = lane >> 2;
    const int tig  = lane & 3;

    const int row0   = blockIdx.y * 256;
    const int colblk = blockIdx.x;           // 0..23
    const int sel    = colblk >> 3;
    const int ncol   = (colblk & 7) * 128;

    const __half* Wh  = g_wh + (size_t)sel * HID * HID;
    const float* bias = (sel == 0) ? bq : (sel == 1) ? bk : bv;
    __half*      dst  = (sel == 0) ? g_q : (sel == 1) ? g_k : g_v;

    const int wm = (warp >> 2) * 64;
    const int wn = (warp & 3) * 32;

    float acc[4][4][4];
#pragma unroll
    for (int i = 0; i < 4; i++)
#pragma unroll
        for (int j = 0; j < 4; j++)
#pragma unroll
            for (int k = 0; k < 4; k++) acc[i][j][k] = 0.f;

    const int lrow = ((lane >> 3) & 1) * 8 + (lane & 7);
    const int lk8  = (lane >> 4) * 8;

    const int ar = tid >> 2;
    const int ac8 = (tid & 3) * 8;
    const int br = tid >> 4;
    const int bc8 = (tid & 15) * 8;

    // prologue: load k0=0 into buf 0
    {
        const uint32_t AsB = qb;
        const uint32_t BsB = qb + 40960;
#pragma unroll
        for (int i = 0; i < 2; i++) {
            int r = ar + i * 128;
            cpa16(AsB + (uint32_t)(r * 40 + ac8) * 2,
                  &g_xh[(size_t)(row0 + r) * HID + ac8]);
        }
        cpa16(BsB + (uint32_t)(br * 136 + bc8) * 2,
              &Wh[(size_t)br * HID + ncol + bc8]);
        CP_COMMIT();
    }

    for (int ki = 0; ki < 32; ki++) {
        const int buf = ki & 1;
        CP_WAIT0();
        __syncthreads();
        if (ki < 31) {
            const int k0 = (ki + 1) * 32;
            const uint32_t AsB = qb + (buf ^ 1) * 20480;
            const uint32_t BsB = qb + 40960 + (buf ^ 1) * 8704;
#pragma unroll
            for (int i = 0; i < 2; i++) {
                int r = ar + i * 128;
                cpa16(AsB + (uint32_t)(r * 40 + ac8) * 2,
                      &g_xh[(size_t)(row0 + r) * HID + k0 + ac8]);
            }
            cpa16(BsB + (uint32_t)(br * 136 + bc8) * 2,
                  &Wh[(size_t)(k0 + br) * HID + ncol + bc8]);
            CP_COMMIT();
        }
        const uint32_t AsB = qb + buf * 20480;
        const uint32_t BsB = qb + 40960 + buf * 8704;

#pragma unroll
        for (int ks = 0; ks < 2; ks++) {
            const int kb = ks * 16;
            uint32_t a[4][4];
#pragma unroll
            for (int mt = 0; mt < 4; mt++)
                ldsm4(a[mt], AsB + (uint32_t)((wm + mt * 16 + lrow) * 40 + kb + lk8) * 2);
            uint32_t b[2][4];
#pragma unroll
            for (int nb = 0; nb < 2; nb++)
                ldsm4t(b[nb], BsB + (uint32_t)((kb + lrow) * 136 + wn + nb * 16 + lk8) * 2);
#pragma unroll
            for (int mt = 0; mt < 4; mt++)
#pragma unroll
                for (int nt = 0; nt < 4; nt++)
                    mma16(acc[mt][nt], a[mt], &b[nt >> 1][(nt & 1) * 2]);
        }
    }

    const int bidx = row0 >> 11;
#pragma unroll
    for (int mt = 0; mt < 4; mt++) {
        int r0 = row0 + wm + mt * 16 + g;
        int s0 = r0 & (SEQ - 1);
#pragma unroll
        for (int nt = 0; nt < 4; nt++) {
            int cc = wn + nt * 8 + 2 * tig;
            int h  = (ncol + cc) >> 6;
            int d  = (ncol + cc) & 63;
            float bf0 = bias[ncol + cc], bf1 = bias[ncol + cc + 1];
            __half* p = dst + (((size_t)bidx * NH + h) * SEQ + s0) * HD + d;
            *(__half2*)p            = f22h(acc[mt][nt][0] + bf0, acc[mt][nt][1] + bf1);
            *(__half2*)(p + 8 * HD) = f22h(acc[mt][nt][2] + bf0, acc[mt][nt][3] + bf1);
        }
    }
}

// ---------------------------------------------------------------------------
// Kernel 2: flash attention. Br=64, Bc=64, 128 threads, 4 warps (2 row x 2 col).
// Split-k PV with in-register P (C->A fragment repack) + Q fragments hoisted
// to registers. cp.async double-buffered K/V/mask. Final O combine across wc.
// Dynamic smem: Qs 64x72h | Kb 2x64x72h | Vb 2x64x72h | Ms 2x64f | RM/RS 128f each
// ---------------------------------------------------------------------------
#define FA_SMEM (46080 + 1536)

__global__ __launch_bounds__(128, 3) void flash_attn(
    const float* __restrict__ mask, float* __restrict__ out)
{
    extern __shared__ __align__(16) __half dsm[];
    float* Ms = (float*)((char*)dsm + 46080);
    float* RM = Ms + 128;
    float* RS = RM + 128;
    const uint32_t sb  = sptr(dsm);
    const uint32_t KbB = sb + 9216;
    const uint32_t VbB = sb + 27648;
    const uint32_t MsB = sb + 46080;

    const int b  = blockIdx.z;
    const int h  = blockIdx.y;
    const int q0 = blockIdx.x * 64;

    const int tid  = threadIdx.x;
    const int warp = tid >> 5;
    const int lane = tid & 31;
    const int g    = lane >> 2;
    const int tig  = lane & 3;
    const int wr   = warp >> 1;
    const int wc   = warp & 1;
    const int qr   = wr * 32;
    const int scb  = wc * 32;        // this warp's S-col / PV k-half base

    const int lrow = ((lane >> 3) & 1) * 8 + (lane & 7);
    const int lk8  = (lane >> 4) * 8;
    const int bn   = (lane >> 4) * 8 + (lane & 7);
    const int bk8  = ((lane >> 3) & 1) * 8;

    const __half* Qg = g_q + ((size_t)(b * NH + h) * SEQ) * HD;
    const __half* Kg = g_k + ((size_t)(b * NH + h) * SEQ) * HD;
    const __half* Vg = g_v + ((size_t)(b * NH + h) * SEQ) * HD;
    const float*  mk = mask + b * SEQ;

    // Prologue: async load Q + K0 + V0 + M0
#pragma unroll
    for (int i = 0; i < 4; i++) {
        int lin = tid + i * 128;
        int r   = lin >> 3;
        int c8  = (lin & 7) * 8;
        uint32_t so = (uint32_t)(r * 72 + c8) * 2;
        cpa16(sb  + so, &Qg[(size_t)(q0 + r) * HD + c8]);
        cpa16(KbB + so, &Kg[(size_t)r * HD + c8]);
        cpa16(VbB + so, &Vg[(size_t)r * HD + c8]);
    }
    if (tid < 64) cpa4(MsB + tid * 4, &mk[tid]);
    CP_COMMIT();
    CP_WAIT0();
    __syncthreads();

    // Hoist Q fragments (loop-invariant)
    uint32_t aq[2][4][4];
#pragma unroll
    for (int mt = 0; mt < 2; mt++)
#pragma unroll
        for (int kk = 0; kk < 4; kk++)
            ldsm4(aq[mt][kk], sb + (uint32_t)((qr + mt * 16 + lrow) * 72 + kk * 16 + lk8) * 2);

    float o[2][8][4];
#pragma unroll
    for (int mt = 0; mt < 2; mt++)
#pragma unroll
        for (int nt = 0; nt < 8; nt++)
#pragma unroll
            for (int j = 0; j < 4; j++) o[mt][nt][j] = 0.f;

    float mrow[2][2] = {{-1e30f, -1e30f}, {-1e30f, -1e30f}};
    float lrowv[2][2] = {{0.f, 0.f}, {0.f, 0.f}};
    const float C1  = 0.18033688011112042f;     // 0.125 * log2(e)
    const float L2E = 1.4426950408889634f;

    for (int it = 0; it < 32; it++) {
        const int buf = it & 1;
        if (it > 0) {
            CP_WAIT0();
            __syncthreads();
        }
        if (it < 31) {
            const int nb = buf ^ 1;
            const int kc = (it + 1) * 64;
#pragma unroll
            for (int i = 0; i < 4; i++) {
                int lin = tid + i * 128;
                int r   = lin >> 3;
                int c8  = (lin & 7) * 8;
                uint32_t so = (uint32_t)(nb * 9216 + (r * 72 + c8) * 2);
                cpa16(KbB + so, &Kg[(size_t)(kc + r) * HD + c8]);
                cpa16(VbB + so, &Vg[(size_t)(kc + r) * HD + c8]);
            }
            if (tid < 64) cpa4(MsB + (nb * 64 + tid) * 4, &mk[kc + tid]);
            CP_COMMIT();
        }
        const uint32_t Ku = KbB + buf * 9216;
        const uint32_t Vu = VbB + buf * 9216;
        const float* Mb = Ms + buf * 64;

        // ---- S = Q K^T : 32x32 per warp (Q frags in regs) ----
        float s[2][4][4];
#pragma unroll
        for (int mt = 0; mt < 2; mt++)
#pragma unroll
            for (int nt = 0; nt < 4; nt++)
#pragma unroll
                for (int j = 0; j < 4; j++) s[mt][nt][j] = 0.f;

#pragma unroll
        for (int kk = 0; kk < 4; kk++) {
            const int kb = kk * 16;
            uint32_t bm[2][4];
            ldsm4(bm[0], Ku + (uint32_t)((scb      + bn) * 72 + kb + bk8) * 2);
            ldsm4(bm[1], Ku + (uint32_t)((scb + 16 + bn) * 72 + kb + bk8) * 2);
#pragma unroll
            for (int mt = 0; mt < 2; mt++)
#pragma unroll
                for (int nt = 0; nt < 4; nt++)
                    mma16(s[mt][nt], aq[mt][kk], &bm[nt >> 1][(nt & 1) * 2]);
        }

        // ---- exp2-domain scale + mask + partial row max ----
        float rm[2][2] = {{-1e30f, -1e30f}, {-1e30f, -1e30f}};
#pragma unroll
        for (int mt = 0; mt < 2; mt++)
#pragma unroll
            for (int nt = 0; nt < 4; nt++) {
                int col = scb + nt * 8 + 2 * tig;
                float mv0 = Mb[col] * L2E, mv1 = Mb[col + 1] * L2E;
                s[mt][nt][0] = s[mt][nt][0] * C1 + mv0;
                s[mt][nt][1] = s[mt][nt][1] * C1 + mv1;
                s[mt][nt][2] = s[mt][nt][2] * C1 + mv0;
                s[mt][nt][3] = s[mt][nt][3] * C1 + mv1;
                rm[mt][0] = fmaxf(rm[mt][0], fmaxf(s[mt][nt][0], s[mt][nt][1]));
                rm[mt][1] = fmaxf(rm[mt][1], fmaxf(s[mt][nt][2], s[mt][nt][3]));
            }
#pragma unroll
        for (int mt = 0; mt < 2; mt++)
#pragma unroll
            for (int hh = 0; hh < 2; hh++) {
                rm[mt][hh] = fmaxf(rm[mt][hh], __shfl_xor_sync(0xffffffffu, rm[mt][hh], 1));
                rm[mt][hh] = fmaxf(rm[mt][hh], __shfl_xor_sync(0xffffffffu, rm[mt][hh], 2));
            }
        if (tig == 0) {
#pragma unroll
            for (int mt = 0; mt < 2; mt++) {
                RM[wc * 64 + qr + mt * 16 + g    ] = rm[mt][0];
                RM[wc * 64 + qr + mt * 16 + g + 8] = rm[mt][1];
            }
        }
        __syncthreads();

        // ---- combine maxes, exp2, pack P into A-fragment registers ----
        float alpha[2][2];
#pragma unroll
        for (int mt = 0; mt < 2; mt++)
#pragma unroll
            for (int hh = 0; hh < 2; hh++) {
                int row = qr + mt * 16 + g + hh * 8;
                float mb = fmaxf(RM[row], RM[64 + row]);
                float mn = fmaxf(mrow[mt][hh], mb);
                alpha[mt][hh] = ex2(mrow[mt][hh] - mn);
                mrow[mt][hh] = mn;
            }
        float sum[2][2] = {{0.f, 0.f}, {0.f, 0.f}};
        uint32_t ap[2][2][4];
#pragma unroll
        for (int mt = 0; mt < 2; mt++)
#pragma unroll
            for (int nt = 0; nt < 4; nt++) {
                float p0 = ex2(s[mt][nt][0] - mrow[mt][0]);
                float p1 = ex2(s[mt][nt][1] - mrow[mt][0]);
                float p2 = ex2(s[mt][nt][2] - mrow[mt][1]);
                float p3 = ex2(s[mt][nt][3] - mrow[mt][1]);
                sum[mt][0] += p0 + p1;
                sum[mt][1] += p2 + p3;
                const int kk = nt >> 1;
                if (nt & 1) {
                    ap[mt][kk][2] = f22hu(p0, p1);
                    ap[mt][kk][3] = f22hu(p2, p3);
                } else {
                    ap[mt][kk][0] = f22hu(p0, p1);
                    ap[mt][kk][1] = f22hu(p2, p3);
                }
            }
#pragma unroll
        for (int mt = 0; mt < 2; mt++)
#pragma unroll
            for (int hh = 0; hh < 2; hh++) {
                sum[mt][hh] += __shfl_xor_sync(0xffffffffu, sum[mt][hh], 1);
                sum[mt][hh] += __shfl_xor_sync(0xffffffffu, sum[mt][hh], 2);
            }
        if (tig == 0) {
#pragma unroll
            for (int mt = 0; mt < 2; mt++) {
                RS[wc * 64 + qr + mt * 16 + g    ] = sum[mt][0];
                RS[wc * 64 + qr + mt * 16 + g + 8] = sum[mt][1];
            }
        }
        __syncthreads();

        // ---- l update + O rescale ----
#pragma unroll
        for (int mt = 0; mt < 2; mt++)
#pragma unroll
            for (int hh = 0; hh < 2; hh++) {
                int row = qr + mt * 16 + g + hh * 8;
                lrowv[mt][hh] = lrowv[mt][hh] * alpha[mt][hh] + RS[row] + RS[64 + row];
            }
#pragma unroll
        for (int mt = 0; mt < 2; mt++)
#pragma unroll
            for (int nt = 0; nt < 8; nt++) {
                o[mt][nt][0] *= alpha[mt][0];
                o[mt][nt][1] *= alpha[mt][0];
                o[mt][nt][2] *= alpha[mt][1];
                o[mt][nt][3] *= alpha[mt][1];
            }

        // ---- O += P V : P in registers, k-half = this warp's S cols ----
#pragma unroll
        for (int kk = 0; kk < 2; kk++) {
            const int kbg = scb + kk * 16;
#pragma unroll
            for (int db = 0; db < 4; db++) {
                uint32_t bv4[4];
                ldsm4t(bv4, Vu + (uint32_t)((kbg + lrow) * 72 + db * 16 + lk8) * 2);
                mma16(o[0][db * 2    ], ap[0][kk], &bv4[0]);
                mma16(o[1][db * 2    ], ap[1][kk], &bv4[0]);
                mma16(o[0][db * 2 + 1], ap[0][kk], &bv4[2]);
                mma16(o[1][db * 2 + 1], ap[1][kk], &bv4[2]);
            }
        }
    }

    // ---- combine the two k-half O partials, normalize, write ----
    float* cb = (float*)dsm;   // 64 x 68 f32 overlay (17.4KB, Q/K dead)
    __syncthreads();
    if (wc == 1) {
#pragma unroll
        for (int mt = 0; mt < 2; mt++)
#pragma unroll
            for (int nt = 0; nt < 8; nt++) {
                int r0  = qr + mt * 16 + g;
                int col = nt * 8 + 2 * tig;
                *(float2*)&cb[r0 * 68 + col]       = make_float2(o[mt][nt][0], o[mt][nt][1]);
                *(float2*)&cb[(r0 + 8) * 68 + col] = make_float2(o[mt][nt][2], o[mt][nt][3]);
            }
    }
    __syncthreads();
    if (wc == 0) {
#pragma unroll
        for (int mt = 0; mt < 2; mt++) {
            float inv0 = 1.f / lrowv[mt][0];
            float inv1 = 1.f / lrowv[mt][1];
            int r0 = qr + mt * 16 + g;
            float* p0 = out + ((size_t)(b * SEQ + q0 + r0    )) * HID + h * HD;
            float* p1 = out + ((size_t)(b * SEQ + q0 + r0 + 8)) * HID + h * HD;
#pragma unroll
            for (int nt = 0; nt < 8; nt++) {
                int col = nt * 8 + 2 * tig;
                float2 e0 = *(float2*)&cb[r0 * 68 + col];
                float2 e1 = *(float2*)&cb[(r0 + 8) * 68 + col];
                *(float2*)&p0[col] = make_float2((o[mt][nt][0] + e0.x) * inv0,
                                                 (o[mt][nt][1] + e0.y) * inv0);
                *(float2*)&p1[col] = make_float2((o[mt][nt][2] + e1.x) * inv1,
                                                 (o[mt][nt][3] + e1.y) * inv1);
            }
        }
    }
}

// ---------------------------------------------------------------------------
extern "C" void kernel_launch(void* const* d_in, const int* in_sizes, int n_in,
                              void* d_out, int out_size)
{
    const float* X    = (const float*)d_in[0];
    const float* mask = (const float*)d_in[1];
    const float* Wq   = (const float*)d_in[2];
    const float* bq   = (const float*)d_in[3];
    const float* Wk   = (const float*)d_in[4];
    const float* bk   = (const float*)d_in[5];
    const float* Wv   = (const float*)d_in[6];
    const float* bv   = (const float*)d_in[7];
    float* out = (float*)d_out;

    cudaFuncSetAttribute(flash_attn, cudaFuncAttributeMaxDynamicSharedMemorySize,
                         FA_SMEM);
    cudaFuncSetAttribute(qkv_gemm, cudaFuncAttributeMaxDynamicSharedMemorySize,
                         QKV_SMEM);

    const int XG = (Bsz*SEQ*HID) / 4;
    const int WG = (HID*HID) / 4;
    int cvt_blocks = (XG + 3 * WG + 255) / 256;
    to_half<<<cvt_blocks, 256>>>(X, Wq, Wk, Wv);

    dim3 g1(24, 32);
    qkv_gemm<<<g1, 512, QKV_SMEM>>>(bq, bk, bv);

    dim3 g2(32, NH, Bsz);
    flash_attn<<<g2, 128, FA_SMEM>>>(mask, out);
}

// round 11
// speedup vs baseline: 11.1759x; 1.0310x over previous
#include <cuda_runtime.h>
#include <cuda_fp16.h>
#include <math.h>
#include <stdint.h>

#define Bsz 4
#define SEQ 2048
#define HID 1024
#define NH 16
#define HD 64

// fp16 scratch
__device__ __half g_q[Bsz*NH*SEQ*HD];
__device__ __half g_k[Bsz*NH*SEQ*HD];
__device__ __half g_v[Bsz*NH*SEQ*HD];
__device__ __half g_xh[(size_t)Bsz*SEQ*HID];
__device__ __half g_wh[3*HID*HID];

// ---------------------------------------------------------------------------
__device__ __forceinline__ uint32_t sptr(const void* p) {
    return (uint32_t)__cvta_generic_to_shared(p);
}
__device__ __forceinline__ void ldsm4(uint32_t* r, uint32_t a) {
    asm volatile("ldmatrix.sync.aligned.m8n8.x4.shared.b16 {%0,%1,%2,%3}, [%4];"
        : "=r"(r[0]), "=r"(r[1]), "=r"(r[2]), "=r"(r[3]) : "r"(a));
}
__device__ __forceinline__ void ldsm4t(uint32_t* r, uint32_t a) {
    asm volatile("ldmatrix.sync.aligned.m8n8.x4.trans.shared.b16 {%0,%1,%2,%3}, [%4];"
        : "=r"(r[0]), "=r"(r[1]), "=r"(r[2]), "=r"(r[3]) : "r"(a));
}
__device__ __forceinline__ void mma16(float* c, const uint32_t* a, const uint32_t* b) {
    asm volatile(
        "mma.sync.aligned.m16n8k16.row.col.f32.f16.f16.f32 "
        "{%0,%1,%2,%3},{%4,%5,%6,%7},{%8,%9},{%0,%1,%2,%3};"
        : "+f"(c[0]), "+f"(c[1]), "+f"(c[2]), "+f"(c[3])
        : "r"(a[0]), "r"(a[1]), "r"(a[2]), "r"(a[3]), "r"(b[0]), "r"(b[1]));
}
__device__ __forceinline__ __half2 f22h(float x, float y) {
    return __float22half2_rn(make_float2(x, y));
}
__device__ __forceinline__ uint32_t f22hu(float x, float y) {
    __half2 h = __float22half2_rn(make_float2(x, y));
    return *(uint32_t*)&h;
}
__device__ __forceinline__ float ex2(float x) {
    float r; asm("ex2.approx.f32 %0, %1;" : "=f"(r) : "f"(x)); return r;
}
__device__ __forceinline__ void cpa16(uint32_t d, const void* s) {
    asm volatile("cp.async.cg.shared.global [%0], [%1], 16;" :: "r"(d), "l"(s));
}
__device__ __forceinline__ void cpa4(uint32_t d, const void* s) {
    asm volatile("cp.async.ca.shared.global [%0], [%1], 4;" :: "r"(d), "l"(s));
}
#define CP_COMMIT() asm volatile("cp.async.commit_group;")
#define CP_WAIT0()  asm volatile("cp.async.wait_group 0;")

// ---------------------------------------------------------------------------
// Kernel 0: convert X, Wq, Wk, Wv to fp16 scratch.
// ---------------------------------------------------------------------------
__global__ __launch_bounds__(256) void to_half(
    const float* __restrict__ X, const float* __restrict__ Wq,
    const float* __restrict__ Wk, const float* __restrict__ Wv)
{
    const int XG = (Bsz*SEQ*HID) / 4;
    const int WG = (HID*HID) / 4;
    int idx = blockIdx.x * blockDim.x + threadIdx.x;
    const float4* src;
    __half* dst;
    if (idx < XG)             { src = (const float4*)X  + idx;               dst = g_xh + (size_t)idx * 4; }
    else if (idx < XG + WG)   { src = (const float4*)Wq + (idx - XG);        dst = g_wh + (size_t)(idx - XG) * 4; }
    else if (idx < XG + 2*WG) { src = (const float4*)Wk + (idx - XG - WG);   dst = g_wh + (size_t)HID*HID + (size_t)(idx - XG - WG) * 4; }
    else if (idx < XG + 3*WG) { src = (const float4*)Wv + (idx - XG - 2*WG); dst = g_wh + (size_t)2*HID*HID + (size_t)(idx - XG - 2*WG) * 4; }
    else return;
    float4 v = *src;
    __half2 lo = f22h(v.x, v.y), hi = f22h(v.z, v.w);
    uint2 pack;
    pack.x = *(uint32_t*)&lo;
    pack.y = *(uint32_t*)&hi;
    *(uint2*)dst = pack;
}

// ---------------------------------------------------------------------------
// Kernel 1: fused QKV projection, fp16, BM=256 x BN=128, BK=32, 512 threads,
// cp.async double-buffered K-loop. (unchanged from R10)
// ---------------------------------------------------------------------------
#define QKV_SMEM 58368

__global__ __launch_bounds__(512) void qkv_gemm(
    const float* __restrict__ bq, const float* __restrict__ bk,
    const float* __restrict__ bv)
{
    extern __shared__ __align__(16) __half qsm[];
    const uint32_t qb = sptr(qsm);

    const int tid  = threadIdx.x;
    const int warp = tid >> 5;
    const int lane = tid & 31;
    const int g    = lane >> 2;
    const int tig  = lane & 3;

    const int row0   = blockIdx.y * 256;
    const int colblk = blockIdx.x;
    const int sel    = colblk >> 3;
    const int ncol   = (colblk & 7) * 128;

    const __half* Wh  = g_wh + (size_t)sel * HID * HID;
    const float* bias = (sel == 0) ? bq : (sel == 1) ? bk : bv;
    __half*      dst  = (sel == 0) ? g_q : (sel == 1) ? g_k : g_v;

    const int wm = (warp >> 2) * 64;
    const int wn = (warp & 3) * 32;

    float acc[4][4][4];
#pragma unroll
    for (int i = 0; i < 4; i++)
#pragma unroll
        for (int j = 0; j < 4; j++)
#pragma unroll
            for (int k = 0; k < 4; k++) acc[i][j][k] = 0.f;

    const int lrow = ((lane >> 3) & 1) * 8 + (lane & 7);
    const int lk8  = (lane >> 4) * 8;

    const int ar = tid >> 2;
    const int ac8 = (tid & 3) * 8;
    const int br = tid >> 4;
    const int bc8 = (tid & 15) * 8;

    {
        const uint32_t AsB = qb;
        const uint32_t BsB = qb + 40960;
#pragma unroll
        for (int i = 0; i < 2; i++) {
            int r = ar + i * 128;
            cpa16(AsB + (uint32_t)(r * 40 + ac8) * 2,
                  &g_xh[(size_t)(row0 + r) * HID + ac8]);
        }
        cpa16(BsB + (uint32_t)(br * 136 + bc8) * 2,
              &Wh[(size_t)br * HID + ncol + bc8]);
        CP_COMMIT();
    }

    for (int ki = 0; ki < 32; ki++) {
        const int buf = ki & 1;
        CP_WAIT0();
        __syncthreads();
        if (ki < 31) {
            const int k0 = (ki + 1) * 32;
            const uint32_t AsB = qb + (buf ^ 1) * 20480;
            const uint32_t BsB = qb + 40960 + (buf ^ 1) * 8704;
#pragma unroll
            for (int i = 0; i < 2; i++) {
                int r = ar + i * 128;
                cpa16(AsB + (uint32_t)(r * 40 + ac8) * 2,
                      &g_xh[(size_t)(row0 + r) * HID + k0 + ac8]);
            }
            cpa16(BsB + (uint32_t)(br * 136 + bc8) * 2,
                  &Wh[(size_t)(k0 + br) * HID + ncol + bc8]);
            CP_COMMIT();
        }
        const uint32_t AsB = qb + buf * 20480;
        const uint32_t BsB = qb + 40960 + buf * 8704;

#pragma unroll
        for (int ks = 0; ks < 2; ks++) {
            const int kb = ks * 16;
            uint32_t a[4][4];
#pragma unroll
            for (int mt = 0; mt < 4; mt++)
                ldsm4(a[mt], AsB + (uint32_t)((wm + mt * 16 + lrow) * 40 + kb + lk8) * 2);
            uint32_t b[2][4];
#pragma unroll
            for (int nb = 0; nb < 2; nb++)
                ldsm4t(b[nb], BsB + (uint32_t)((kb + lrow) * 136 + wn + nb * 16 + lk8) * 2);
#pragma unroll
            for (int mt = 0; mt < 4; mt++)
#pragma unroll
                for (int nt = 0; nt < 4; nt++)
                    mma16(acc[mt][nt], a[mt], &b[nt >> 1][(nt & 1) * 2]);
        }
    }

    const int bidx = row0 >> 11;
#pragma unroll
    for (int mt = 0; mt < 4; mt++) {
        int r0 = row0 + wm + mt * 16 + g;
        int s0 = r0 & (SEQ - 1);
#pragma unroll
        for (int nt = 0; nt < 4; nt++) {
            int cc = wn + nt * 8 + 2 * tig;
            int h  = (ncol + cc) >> 6;
            int d  = (ncol + cc) & 63;
            float bf0 = bias[ncol + cc], bf1 = bias[ncol + cc + 1];
            __half* p = dst + (((size_t)bidx * NH + h) * SEQ + s0) * HD + d;
            *(__half2*)p            = f22h(acc[mt][nt][0] + bf0, acc[mt][nt][1] + bf1);
            *(__half2*)(p + 8 * HD) = f22h(acc[mt][nt][2] + bf0, acc[mt][nt][3] + bf1);
        }
    }
}

// ---------------------------------------------------------------------------
// Kernel 2: flash attention. Br=64, Bc=64, 128 threads, 4 warps (2 row x 2 col).
// DEFERRED-MAX split-k: each warp runs a fully warp-local online softmax over
// its own 32 columns (own m, own l, own O partial). NO cross-warp sync inside
// the loop beyond the single buffer barrier. Exact correction applied once at
// the end: O = (O0*2^{m0-M} + O1*2^{m1-M}) / (l0*2^{m0-M} + l1*2^{m1-M}).
// P stays in registers (C->A repack), Q fragments hoisted.
// Dynamic smem: Qs 64x72h | Kb 2x64x72h | Vb 2x64x72h | Ms 2x64f | RM/RS 128f
// ---------------------------------------------------------------------------
#define FA_SMEM (46080 + 1536)

__global__ __launch_bounds__(128, 3) void flash_attn(
    const float* __restrict__ mask, float* __restrict__ out)
{
    extern __shared__ __align__(16) __half dsm[];
    float* Ms = (float*)((char*)dsm + 46080);
    float* RM = Ms + 128;          // final combine: m of wc==1, per row
    float* RS = RM + 128;          // final combine: l of wc==1, per row
    const uint32_t sb  = sptr(dsm);
    const uint32_t KbB = sb + 9216;
    const uint32_t VbB = sb + 27648;
    const uint32_t MsB = sb + 46080;

    const int b  = blockIdx.z;
    const int h  = blockIdx.y;
    const int q0 = blockIdx.x * 64;

    const int tid  = threadIdx.x;
    const int warp = tid >> 5;
    const int lane = tid & 31;
    const int g    = lane >> 2;
    const int tig  = lane & 3;
    const int wr   = warp >> 1;
    const int wc   = warp & 1;
    const int qr   = wr * 32;
    const int scb  = wc * 32;

    const int lrow = ((lane >> 3) & 1) * 8 + (lane & 7);
    const int lk8  = (lane >> 4) * 8;
    const int bn   = (lane >> 4) * 8 + (lane & 7);
    const int bk8  = ((lane >> 3) & 1) * 8;

    const __half* Qg = g_q + ((size_t)(b * NH + h) * SEQ) * HD;
    const __half* Kg = g_k + ((size_t)(b * NH + h) * SEQ) * HD;
    const __half* Vg = g_v + ((size_t)(b * NH + h) * SEQ) * HD;
    const float*  mk = mask + b * SEQ;

    // Prologue: async load Q + K0 + V0 + M0
#pragma unroll
    for (int i = 0; i < 4; i++) {
        int lin = tid + i * 128;
        int r   = lin >> 3;
        int c8  = (lin & 7) * 8;
        uint32_t so = (uint32_t)(r * 72 + c8) * 2;
        cpa16(sb  + so, &Qg[(size_t)(q0 + r) * HD + c8]);
        cpa16(KbB + so, &Kg[(size_t)r * HD + c8]);
        cpa16(VbB + so, &Vg[(size_t)r * HD + c8]);
    }
    if (tid < 64) cpa4(MsB + tid * 4, &mk[tid]);
    CP_COMMIT();
    CP_WAIT0();
    __syncthreads();

    // Hoist Q fragments (loop-invariant)
    uint32_t aq[2][4][4];
#pragma unroll
    for (int mt = 0; mt < 2; mt++)
#pragma unroll
        for (int kk = 0; kk < 4; kk++)
            ldsm4(aq[mt][kk], sb + (uint32_t)((qr + mt * 16 + lrow) * 72 + kk * 16 + lk8) * 2);

    float o[2][8][4];
#pragma unroll
    for (int mt = 0; mt < 2; mt++)
#pragma unroll
        for (int nt = 0; nt < 8; nt++)
#pragma unroll
            for (int j = 0; j < 4; j++) o[mt][nt][j] = 0.f;

    float mrow[2][2] = {{-1e30f, -1e30f}, {-1e30f, -1e30f}};   // warp-local
    float lrowv[2][2] = {{0.f, 0.f}, {0.f, 0.f}};
    const float C1  = 0.18033688011112042f;     // 0.125 * log2(e)
    const float L2E = 1.4426950408889634f;

    for (int it = 0; it < 32; it++) {
        const int buf = it & 1;
        if (it > 0) {
            CP_WAIT0();
            __syncthreads();   // sole per-iter barrier
        }
        if (it < 31) {
            const int nb = buf ^ 1;
            const int kc = (it + 1) * 64;
#pragma unroll
            for (int i = 0; i < 4; i++) {
                int lin = tid + i * 128;
                int r   = lin >> 3;
                int c8  = (lin & 7) * 8;
                uint32_t so = (uint32_t)(nb * 9216 + (r * 72 + c8) * 2);
                cpa16(KbB + so, &Kg[(size_t)(kc + r) * HD + c8]);
                cpa16(VbB + so, &Vg[(size_t)(kc + r) * HD + c8]);
            }
            if (tid < 64) cpa4(MsB + (nb * 64 + tid) * 4, &mk[kc + tid]);
            CP_COMMIT();
        }
        const uint32_t Ku = KbB + buf * 9216;
        const uint32_t Vu = VbB + buf * 9216;
        const float* Mb = Ms + buf * 64;

        // ---- S = Q K^T : 32x32 per warp ----
        float s[2][4][4];
#pragma unroll
        for (int mt = 0; mt < 2; mt++)
#pragma unroll
            for (int nt = 0; nt < 4; nt++)
#pragma unroll
                for (int j = 0; j < 4; j++) s[mt][nt][j] = 0.f;

#pragma unroll
        for (int kk = 0; kk < 4; kk++) {
            const int kb = kk * 16;
            uint32_t bm[2][4];
            ldsm4(bm[0], Ku + (uint32_t)((scb      + bn) * 72 + kb + bk8) * 2);
            ldsm4(bm[1], Ku + (uint32_t)((scb + 16 + bn) * 72 + kb + bk8) * 2);
#pragma unroll
            for (int mt = 0; mt < 2; mt++)
#pragma unroll
                for (int nt = 0; nt < 4; nt++)
                    mma16(s[mt][nt], aq[mt][kk], &bm[nt >> 1][(nt & 1) * 2]);
        }

        // ---- warp-local scale + mask + row max (quad shuffles only) ----
        float rm[2][2] = {{-1e30f, -1e30f}, {-1e30f, -1e30f}};
#pragma unroll
        for (int mt = 0; mt < 2; mt++)
#pragma unroll
            for (int nt = 0; nt < 4; nt++) {
                int col = scb + nt * 8 + 2 * tig;
                float mv0 = Mb[col] * L2E, mv1 = Mb[col + 1] * L2E;
                s[mt][nt][0] = s[mt][nt][0] * C1 + mv0;
                s[mt][nt][1] = s[mt][nt][1] * C1 + mv1;
                s[mt][nt][2] = s[mt][nt][2] * C1 + mv0;
                s[mt][nt][3] = s[mt][nt][3] * C1 + mv1;
                rm[mt][0] = fmaxf(rm[mt][0], fmaxf(s[mt][nt][0], s[mt][nt][1]));
                rm[mt][1] = fmaxf(rm[mt][1], fmaxf(s[mt][nt][2], s[mt][nt][3]));
            }
        float alpha[2][2];
#pragma unroll
        for (int mt = 0; mt < 2; mt++)
#pragma unroll
            for (int hh = 0; hh < 2; hh++) {
                rm[mt][hh] = fmaxf(rm[mt][hh], __shfl_xor_sync(0xffffffffu, rm[mt][hh], 1));
                rm[mt][hh] = fmaxf(rm[mt][hh], __shfl_xor_sync(0xffffffffu, rm[mt][hh], 2));
                float mn = fmaxf(mrow[mt][hh], rm[mt][hh]);
                alpha[mt][hh] = ex2(mrow[mt][hh] - mn);
                mrow[mt][hh] = mn;
            }

        // ---- exp2 + P pack (in registers) + l update ----
        float sum[2][2] = {{0.f, 0.f}, {0.f, 0.f}};
        uint32_t ap[2][2][4];
#pragma unroll
        for (int mt = 0; mt < 2; mt++)
#pragma unroll
            for (int nt = 0; nt < 4; nt++) {
                float p0 = ex2(s[mt][nt][0] - mrow[mt][0]);
                float p1 = ex2(s[mt][nt][1] - mrow[mt][0]);
                float p2 = ex2(s[mt][nt][2] - mrow[mt][1]);
                float p3 = ex2(s[mt][nt][3] - mrow[mt][1]);
                sum[mt][0] += p0 + p1;
                sum[mt][1] += p2 + p3;
                const int kk = nt >> 1;
                if (nt & 1) {
                    ap[mt][kk][2] = f22hu(p0, p1);
                    ap[mt][kk][3] = f22hu(p2, p3);
                } else {
                    ap[mt][kk][0] = f22hu(p0, p1);
                    ap[mt][kk][1] = f22hu(p2, p3);
                }
            }
#pragma unroll
        for (int mt = 0; mt < 2; mt++)
#pragma unroll
            for (int hh = 0; hh < 2; hh++) {
                sum[mt][hh] += __shfl_xor_sync(0xffffffffu, sum[mt][hh], 1);
                sum[mt][hh] += __shfl_xor_sync(0xffffffffu, sum[mt][hh], 2);
                lrowv[mt][hh] = lrowv[mt][hh] * alpha[mt][hh] + sum[mt][hh];
            }

        // ---- O rescale + PV (k-half = this warp's S cols) ----
#pragma unroll
        for (int mt = 0; mt < 2; mt++)
#pragma unroll
            for (int nt = 0; nt < 8; nt++) {
                o[mt][nt][0] *= alpha[mt][0];
                o[mt][nt][1] *= alpha[mt][0];
                o[mt][nt][2] *= alpha[mt][1];
                o[mt][nt][3] *= alpha[mt][1];
            }
#pragma unroll
        for (int kk = 0; kk < 2; kk++) {
            const int kbg = scb + kk * 16;
#pragma unroll
            for (int db = 0; db < 4; db++) {
                uint32_t bv4[4];
                ldsm4t(bv4, Vu + (uint32_t)((kbg + lrow) * 72 + db * 16 + lk8) * 2);
                mma16(o[0][db * 2    ], ap[0][kk], &bv4[0]);
                mma16(o[1][db * 2    ], ap[1][kk], &bv4[0]);
                mma16(o[0][db * 2 + 1], ap[0][kk], &bv4[2]);
                mma16(o[1][db * 2 + 1], ap[1][kk], &bv4[2]);
            }
        }
    }

    // ---- final combine: merge (O, m, l) across the two col-half warps ----
    float* cb = (float*)dsm;   // 64 x 68 f32 overlay (Q/K regions dead)
    __syncthreads();
    if (wc == 1) {
#pragma unroll
        for (int mt = 0; mt < 2; mt++) {
#pragma unroll
            for (int nt = 0; nt < 8; nt++) {
                int r0  = qr + mt * 16 + g;
                int col = nt * 8 + 2 * tig;
                *(float2*)&cb[r0 * 68 + col]       = make_float2(o[mt][nt][0], o[mt][nt][1]);
                *(float2*)&cb[(r0 + 8) * 68 + col] = make_float2(o[mt][nt][2], o[mt][nt][3]);
            }
            if (tig == 0) {
#pragma unroll
                for (int hh = 0; hh < 2; hh++) {
                    int row = qr + mt * 16 + g + hh * 8;
                    RM[row] = mrow[mt][hh];
                    RS[row] = lrowv[mt][hh];
                }
            }
        }
    }
    __syncthreads();
    if (wc == 0) {
#pragma unroll
        for (int mt = 0; mt < 2; mt++) {
            float sc0[2], sc1[2], inv[2];
#pragma unroll
            for (int hh = 0; hh < 2; hh++) {
                int row = qr + mt * 16 + g + hh * 8;
                float m1 = RM[row], l1 = RS[row];
                float M  = fmaxf(mrow[mt][hh], m1);
                sc0[hh] = ex2(mrow[mt][hh] - M);
                sc1[hh] = ex2(m1 - M);
                inv[hh] = 1.f / (lrowv[mt][hh] * sc0[hh] + l1 * sc1[hh]);
            }
            int r0 = qr + mt * 16 + g;
            float* p0 = out + ((size_t)(b * SEQ + q0 + r0    )) * HID + h * HD;
            float* p1 = out + ((size_t)(b * SEQ + q0 + r0 + 8)) * HID + h * HD;
#pragma unroll
            for (int nt = 0; nt < 8; nt++) {
                int col = nt * 8 + 2 * tig;
                float2 e0 = *(float2*)&cb[r0 * 68 + col];
                float2 e1 = *(float2*)&cb[(r0 + 8) * 68 + col];
                *(float2*)&p0[col] = make_float2(
                    (o[mt][nt][0] * sc0[0] + e0.x * sc1[0]) * inv[0],
                    (o[mt][nt][1] * sc0[0] + e0.y * sc1[0]) * inv[0]);
                *(float2*)&p1[col] = make_float2(
                    (o[mt][nt][2] * sc0[1] + e1.x * sc1[1]) * inv[1],
                    (o[mt][nt][3] * sc0[1] + e1.y * sc1[1]) * inv[1]);
            }
        }
    }
}

// ---------------------------------------------------------------------------
extern "C" void kernel_launch(void* const* d_in, const int* in_sizes, int n_in,
                              void* d_out, int out_size)
{
    const float* X    = (const float*)d_in[0];
    const float* mask = (const float*)d_in[1];
    const float* Wq   = (const float*)d_in[2];
    const float* bq   = (const float*)d_in[3];
    const float* Wk   = (const float*)d_in[4];
    const float* bk   = (const float*)d_in[5];
    const float* Wv   = (const float*)d_in[6];
    const float* bv   = (const float*)d_in[7];
    float* out = (float*)d_out;

    cudaFuncSetAttribute(flash_attn, cudaFuncAttributeMaxDynamicSharedMemorySize,
                         FA_SMEM);
    cudaFuncSetAttribute(qkv_gemm, cudaFuncAttributeMaxDynamicSharedMemorySize,
                         QKV_SMEM);

    const int XG = (Bsz*SEQ*HID) / 4;
    const int WG = (HID*HID) / 4;
    int cvt_blocks = (XG + 3 * WG + 255) / 256;
    to_half<<<cvt_blocks, 256>>>(X, Wq, Wk, Wv);

    dim3 g1(24, 32);
    qkv_gemm<<<g1, 512, QKV_SMEM>>>(bq, bk, bv);

    dim3 g2(32, NH, Bsz);
    flash_attn<<<g2, 128, FA_SMEM>>>(mask, out);
}

// round 12
// speedup vs baseline: 11.1821x; 1.0006x over previous
#include <cuda_runtime.h>
#include <cuda_fp16.h>
#include <math.h>
#include <stdint.h>

#define Bsz 4
#define SEQ 2048
#define HID 1024
#define NH 16
#define HD 64

// fp16 scratch
__device__ __half g_q[Bsz*NH*SEQ*HD];
__device__ __half g_k[Bsz*NH*SEQ*HD];
__device__ __half g_v[Bsz*NH*SEQ*HD];
__device__ __half g_xh[(size_t)Bsz*SEQ*HID];
__device__ __half g_wh[3*HID*HID];

// ---------------------------------------------------------------------------
__device__ __forceinline__ uint32_t sptr(const void* p) {
    return (uint32_t)__cvta_generic_to_shared(p);
}
__device__ __forceinline__ void ldsm4(uint32_t* r, uint32_t a) {
    asm volatile("ldmatrix.sync.aligned.m8n8.x4.shared.b16 {%0,%1,%2,%3}, [%4];"
        : "=r"(r[0]), "=r"(r[1]), "=r"(r[2]), "=r"(r[3]) : "r"(a));
}
__device__ __forceinline__ void ldsm4t(uint32_t* r, uint32_t a) {
    asm volatile("ldmatrix.sync.aligned.m8n8.x4.trans.shared.b16 {%0,%1,%2,%3}, [%4];"
        : "=r"(r[0]), "=r"(r[1]), "=r"(r[2]), "=r"(r[3]) : "r"(a));
}
__device__ __forceinline__ void mma16(float* c, const uint32_t* a, const uint32_t* b) {
    asm volatile(
        "mma.sync.aligned.m16n8k16.row.col.f32.f16.f16.f32 "
        "{%0,%1,%2,%3},{%4,%5,%6,%7},{%8,%9},{%0,%1,%2,%3};"
        : "+f"(c[0]), "+f"(c[1]), "+f"(c[2]), "+f"(c[3])
        : "r"(a[0]), "r"(a[1]), "r"(a[2]), "r"(a[3]), "r"(b[0]), "r"(b[1]));
}
__device__ __forceinline__ __half2 f22h(float x, float y) {
    return __float22half2_rn(make_float2(x, y));
}
__device__ __forceinline__ uint32_t f22hu(float x, float y) {
    __half2 h = __float22half2_rn(make_float2(x, y));
    return *(uint32_t*)&h;
}
__device__ __forceinline__ float ex2(float x) {
    float r; asm("ex2.approx.f32 %0, %1;" : "=f"(r) : "f"(x)); return r;
}
__device__ __forceinline__ void cpa16(uint32_t d, const void* s) {
    asm volatile("cp.async.cg.shared.global [%0], [%1], 16;" :: "r"(d), "l"(s));
}
__device__ __forceinline__ void cpa4(uint32_t d, const void* s) {
    asm volatile("cp.async.ca.shared.global [%0], [%1], 4;" :: "r"(d), "l"(s));
}
#define CP_COMMIT() asm volatile("cp.async.commit_group;")
#define CP_WAIT0()  asm volatile("cp.async.wait_group 0;")
#define CP_WAIT1()  asm volatile("cp.async.wait_group 1;")

// ---------------------------------------------------------------------------
// Kernel 0: convert X, Wq, Wk, Wv to fp16 scratch.
// ---------------------------------------------------------------------------
__global__ __launch_bounds__(256) void to_half(
    const float* __restrict__ X, const float* __restrict__ Wq,
    const float* __restrict__ Wk, const float* __restrict__ Wv)
{
    const int XG = (Bsz*SEQ*HID) / 4;
    const int WG = (HID*HID) / 4;
    int idx = blockIdx.x * blockDim.x + threadIdx.x;
    const float4* src;
    __half* dst;
    if (idx < XG)             { src = (const float4*)X  + idx;               dst = g_xh + (size_t)idx * 4; }
    else if (idx < XG + WG)   { src = (const float4*)Wq + (idx - XG);        dst = g_wh + (size_t)(idx - XG) * 4; }
    else if (idx < XG + 2*WG) { src = (const float4*)Wk + (idx - XG - WG);   dst = g_wh + (size_t)HID*HID + (size_t)(idx - XG - WG) * 4; }
    else if (idx < XG + 3*WG) { src = (const float4*)Wv + (idx - XG - 2*WG); dst = g_wh + (size_t)2*HID*HID + (size_t)(idx - XG - 2*WG) * 4; }
    else return;
    float4 v = *src;
    __half2 lo = f22h(v.x, v.y), hi = f22h(v.z, v.w);
    uint2 pack;
    pack.x = *(uint32_t*)&lo;
    pack.y = *(uint32_t*)&hi;
    *(uint2*)dst = pack;
}

// ---------------------------------------------------------------------------
// Kernel 1: fused QKV projection, fp16, BM=256 x BN=128, BK=32, 512 threads,
// cp.async THREE-stage pipeline (wait_group 1). Dynamic smem:
//   As 3 x 20480B | Bs 3 x 8704B = 87552B
// ---------------------------------------------------------------------------
#define QKV_SMEM 87552

__global__ __launch_bounds__(512) void qkv_gemm(
    const float* __restrict__ bq, const float* __restrict__ bk,
    const float* __restrict__ bv)
{
    extern __shared__ __align__(16) __half qsm[];
    const uint32_t qb = sptr(qsm);
    const uint32_t BsBase = qb + 3 * 20480;

    const int tid  = threadIdx.x;
    const int warp = tid >> 5;
    const int lane = tid & 31;
    const int g    = lane >> 2;
    const int tig  = lane & 3;

    const int row0   = blockIdx.y * 256;
    const int colblk = blockIdx.x;
    const int sel    = colblk >> 3;
    const int ncol   = (colblk & 7) * 128;

    const __half* Wh  = g_wh + (size_t)sel * HID * HID;
    const float* bias = (sel == 0) ? bq : (sel == 1) ? bk : bv;
    __half*      dst  = (sel == 0) ? g_q : (sel == 1) ? g_k : g_v;

    const int wm = (warp >> 2) * 64;
    const int wn = (warp & 3) * 32;

    float acc[4][4][4];
#pragma unroll
    for (int i = 0; i < 4; i++)
#pragma unroll
        for (int j = 0; j < 4; j++)
#pragma unroll
            for (int k = 0; k < 4; k++) acc[i][j][k] = 0.f;

    const int lrow = ((lane >> 3) & 1) * 8 + (lane & 7);
    const int lk8  = (lane >> 4) * 8;

    const int ar  = tid >> 2;
    const int ac8 = (tid & 3) * 8;
    const int br  = tid >> 4;
    const int bc8 = (tid & 15) * 8;

    // prologue: issue stages for ki=0 and ki=1
#pragma unroll
    for (int p = 0; p < 2; p++) {
        const int k0 = p * 32;
        const uint32_t AsB = qb + p * 20480;
        const uint32_t BsB = BsBase + p * 8704;
#pragma unroll
        for (int i = 0; i < 2; i++) {
            int r = ar + i * 128;
            cpa16(AsB + (uint32_t)(r * 40 + ac8) * 2,
                  &g_xh[(size_t)(row0 + r) * HID + k0 + ac8]);
        }
        cpa16(BsB + (uint32_t)(br * 136 + bc8) * 2,
              &Wh[(size_t)(k0 + br) * HID + ncol + bc8]);
        CP_COMMIT();
    }

    for (int ki = 0; ki < 32; ki++) {
        const int st = ki % 3;
        CP_WAIT1();                // group ki complete; group ki+1 may fly
        __syncthreads();
        if (ki < 30) {
            const int k0 = (ki + 2) * 32;
            const int ns = (ki + 2) % 3;
            const uint32_t AsB = qb + ns * 20480;
            const uint32_t BsB = BsBase + ns * 8704;
#pragma unroll
            for (int i = 0; i < 2; i++) {
                int r = ar + i * 128;
                cpa16(AsB + (uint32_t)(r * 40 + ac8) * 2,
                      &g_xh[(size_t)(row0 + r) * HID + k0 + ac8]);
            }
            cpa16(BsB + (uint32_t)(br * 136 + bc8) * 2,
                  &Wh[(size_t)(k0 + br) * HID + ncol + bc8]);
            CP_COMMIT();
        }
        const uint32_t AsB = qb + st * 20480;
        const uint32_t BsB = BsBase + st * 8704;

#pragma unroll
        for (int ks = 0; ks < 2; ks++) {
            const int kb = ks * 16;
            uint32_t a[4][4];
#pragma unroll
            for (int mt = 0; mt < 4; mt++)
                ldsm4(a[mt], AsB + (uint32_t)((wm + mt * 16 + lrow) * 40 + kb + lk8) * 2);
            uint32_t b[2][4];
#pragma unroll
            for (int nb = 0; nb < 2; nb++)
                ldsm4t(b[nb], BsB + (uint32_t)((kb + lrow) * 136 + wn + nb * 16 + lk8) * 2);
#pragma unroll
            for (int mt = 0; mt < 4; mt++)
#pragma unroll
                for (int nt = 0; nt < 4; nt++)
                    mma16(acc[mt][nt], a[mt], &b[nt >> 1][(nt & 1) * 2]);
        }
    }

    const int bidx = row0 >> 11;
#pragma unroll
    for (int mt = 0; mt < 4; mt++) {
        int r0 = row0 + wm + mt * 16 + g;
        int s0 = r0 & (SEQ - 1);
#pragma unroll
        for (int nt = 0; nt < 4; nt++) {
            int cc = wn + nt * 8 + 2 * tig;
            int h  = (ncol + cc) >> 6;
            int d  = (ncol + cc) & 63;
            float bf0 = bias[ncol + cc], bf1 = bias[ncol + cc + 1];
            __half* p = dst + (((size_t)bidx * NH + h) * SEQ + s0) * HD + d;
            *(__half2*)p            = f22h(acc[mt][nt][0] + bf0, acc[mt][nt][1] + bf1);
            *(__half2*)(p + 8 * HD) = f22h(acc[mt][nt][2] + bf0, acc[mt][nt][3] + bf1);
        }
    }
}

// ---------------------------------------------------------------------------
// Kernel 2: flash attention. Br=64, Bc=64, 128 threads, 4 warps (2 row x 2 col).
// Deferred-max split-k (warp-local softmax), in-register P, hoisted Q frags,
// cp.async THREE-stage K/V/mask pipeline (wait_group 1).
// Smem: Qs 9216 | K 3x9216 | V 3x9216 | Ms 3x64f | RM 128f | RS 128f = 66304B
// ---------------------------------------------------------------------------
#define FA_SMEM 66304

__global__ __launch_bounds__(128, 3) void flash_attn(
    const float* __restrict__ mask, float* __restrict__ out)
{
    extern __shared__ __align__(16) __half dsm[];
    const uint32_t sb  = sptr(dsm);
    const uint32_t KbB = sb + 9216;             // 3 stages of 9216B
    const uint32_t VbB = sb + 9216 + 27648;     // 3 stages of 9216B
    const uint32_t MsB = sb + 64512;            // 3 x 64 floats
    float* Ms = (float*)((char*)dsm + 64512);
    float* RM = (float*)((char*)dsm + 65280);
    float* RS = (float*)((char*)dsm + 65792);

    const int b  = blockIdx.z;
    const int h  = blockIdx.y;
    const int q0 = blockIdx.x * 64;

    const int tid  = threadIdx.x;
    const int warp = tid >> 5;
    const int lane = tid & 31;
    const int g    = lane >> 2;
    const int tig  = lane & 3;
    const int wr   = warp >> 1;
    const int wc   = warp & 1;
    const int qr   = wr * 32;
    const int scb  = wc * 32;

    const int lrow = ((lane >> 3) & 1) * 8 + (lane & 7);
    const int lk8  = (lane >> 4) * 8;
    const int bn   = (lane >> 4) * 8 + (lane & 7);
    const int bk8  = ((lane >> 3) & 1) * 8;

    const __half* Qg = g_q + ((size_t)(b * NH + h) * SEQ) * HD;
    const __half* Kg = g_k + ((size_t)(b * NH + h) * SEQ) * HD;
    const __half* Vg = g_v + ((size_t)(b * NH + h) * SEQ) * HD;
    const float*  mk = mask + b * SEQ;

    // Prologue: group0 = Q + K0 + V0 + M0 ; group1 = K1 + V1 + M1
#pragma unroll
    for (int i = 0; i < 4; i++) {
        int lin = tid + i * 128;
        int r   = lin >> 3;
        int c8  = (lin & 7) * 8;
        uint32_t so = (uint32_t)(r * 72 + c8) * 2;
        cpa16(sb  + so, &Qg[(size_t)(q0 + r) * HD + c8]);
        cpa16(KbB + so, &Kg[(size_t)r * HD + c8]);
        cpa16(VbB + so, &Vg[(size_t)r * HD + c8]);
    }
    if (tid < 64) cpa4(MsB + tid * 4, &mk[tid]);
    CP_COMMIT();
#pragma unroll
    for (int i = 0; i < 4; i++) {
        int lin = tid + i * 128;
        int r   = lin >> 3;
        int c8  = (lin & 7) * 8;
        uint32_t so = (uint32_t)(9216 + (r * 72 + c8) * 2);
        cpa16(KbB + so, &Kg[(size_t)(64 + r) * HD + c8]);
        cpa16(VbB + so, &Vg[(size_t)(64 + r) * HD + c8]);
    }
    if (tid < 64) cpa4(MsB + (64 + tid) * 4, &mk[64 + tid]);
    CP_COMMIT();

    CP_WAIT1();          // group0 (Q/K0/V0/M0) complete
    __syncthreads();

    // Hoist Q fragments (loop-invariant)
    uint32_t aq[2][4][4];
#pragma unroll
    for (int mt = 0; mt < 2; mt++)
#pragma unroll
        for (int kk = 0; kk < 4; kk++)
            ldsm4(aq[mt][kk], sb + (uint32_t)((qr + mt * 16 + lrow) * 72 + kk * 16 + lk8) * 2);

    float o[2][8][4];
#pragma unroll
    for (int mt = 0; mt < 2; mt++)
#pragma unroll
        for (int nt = 0; nt < 8; nt++)
#pragma unroll
            for (int j = 0; j < 4; j++) o[mt][nt][j] = 0.f;

    float mrow[2][2] = {{-1e30f, -1e30f}, {-1e30f, -1e30f}};
    float lrowv[2][2] = {{0.f, 0.f}, {0.f, 0.f}};
    const float C1  = 0.18033688011112042f;     // 0.125 * log2(e)
    const float L2E = 1.4426950408889634f;

    for (int it = 0; it < 32; it++) {
        const int st = it % 3;
        if (it > 0) {
            CP_WAIT1();            // group it complete; group it+1 may fly
            __syncthreads();
        }
        if (it < 30) {
            const int ns = (it + 2) % 3;
            const int kc = (it + 2) * 64;
#pragma unroll
            for (int i = 0; i < 4; i++) {
                int lin = tid + i * 128;
                int r   = lin >> 3;
                int c8  = (lin & 7) * 8;
                uint32_t so = (uint32_t)(ns * 9216 + (r * 72 + c8) * 2);
                cpa16(KbB + so, &Kg[(size_t)(kc + r) * HD + c8]);
                cpa16(VbB + so, &Vg[(size_t)(kc + r) * HD + c8]);
            }
            if (tid < 64) cpa4(MsB + (ns * 64 + tid) * 4, &mk[kc + tid]);
            CP_COMMIT();
        }
        const uint32_t Ku = KbB + st * 9216;
        const uint32_t Vu = VbB + st * 9216;
        const float* Mb = Ms + st * 64;

        // ---- S = Q K^T : 32x32 per warp ----
        float s[2][4][4];
#pragma unroll
        for (int mt = 0; mt < 2; mt++)
#pragma unroll
            for (int nt = 0; nt < 4; nt++)
#pragma unroll
                for (int j = 0; j < 4; j++) s[mt][nt][j] = 0.f;

#pragma unroll
        for (int kk = 0; kk < 4; kk++) {
            const int kb = kk * 16;
            uint32_t bm[2][4];
            ldsm4(bm[0], Ku + (uint32_t)((scb      + bn) * 72 + kb + bk8) * 2);
            ldsm4(bm[1], Ku + (uint32_t)((scb + 16 + bn) * 72 + kb + bk8) * 2);
#pragma unroll
            for (int mt = 0; mt < 2; mt++)
#pragma unroll
                for (int nt = 0; nt < 4; nt++)
                    mma16(s[mt][nt], aq[mt][kk], &bm[nt >> 1][(nt & 1) * 2]);
        }

        // ---- warp-local scale + mask + row max ----
        float rm[2][2] = {{-1e30f, -1e30f}, {-1e30f, -1e30f}};
#pragma unroll
        for (int mt = 0; mt < 2; mt++)
#pragma unroll
            for (int nt = 0; nt < 4; nt++) {
                int col = scb + nt * 8 + 2 * tig;
                float mv0 = Mb[col] * L2E, mv1 = Mb[col + 1] * L2E;
                s[mt][nt][0] = s[mt][nt][0] * C1 + mv0;
                s[mt][nt][1] = s[mt][nt][1] * C1 + mv1;
                s[mt][nt][2] = s[mt][nt][2] * C1 + mv0;
                s[mt][nt][3] = s[mt][nt][3] * C1 + mv1;
                rm[mt][0] = fmaxf(rm[mt][0], fmaxf(s[mt][nt][0], s[mt][nt][1]));
                rm[mt][1] = fmaxf(rm[mt][1], fmaxf(s[mt][nt][2], s[mt][nt][3]));
            }
        float alpha[2][2];
#pragma unroll
        for (int mt = 0; mt < 2; mt++)
#pragma unroll
            for (int hh = 0; hh < 2; hh++) {
                rm[mt][hh] = fmaxf(rm[mt][hh], __shfl_xor_sync(0xffffffffu, rm[mt][hh], 1));
                rm[mt][hh] = fmaxf(rm[mt][hh], __shfl_xor_sync(0xffffffffu, rm[mt][hh], 2));
                float mn = fmaxf(mrow[mt][hh], rm[mt][hh]);
                alpha[mt][hh] = ex2(mrow[mt][hh] - mn);
                mrow[mt][hh] = mn;
            }

        // ---- exp2 + P pack + l update ----
        float sum[2][2] = {{0.f, 0.f}, {0.f, 0.f}};
        uint32_t ap[2][2][4];
#pragma unroll
        for (int mt = 0; mt < 2; mt++)
#pragma unroll
            for (int nt = 0; nt < 4; nt++) {
                float p0 = ex2(s[mt][nt][0] - mrow[mt][0]);
                float p1 = ex2(s[mt][nt][1] - mrow[mt][0]);
                float p2 = ex2(s[mt][nt][2] - mrow[mt][1]);
                float p3 = ex2(s[mt][nt][3] - mrow[mt][1]);
                sum[mt][0] += p0 + p1;
                sum[mt][1] += p2 + p3;
                const int kk = nt >> 1;
                if (nt & 1) {
                    ap[mt][kk][2] = f22hu(p0, p1);
                    ap[mt][kk][3] = f22hu(p2, p3);
                } else {
                    ap[mt][kk][0] = f22hu(p0, p1);
                    ap[mt][kk][1] = f22hu(p2, p3);
                }
            }
#pragma unroll
        for (int mt = 0; mt < 2; mt++)
#pragma unroll
            for (int hh = 0; hh < 2; hh++) {
                sum[mt][hh] += __shfl_xor_sync(0xffffffffu, sum[mt][hh], 1);
                sum[mt][hh] += __shfl_xor_sync(0xffffffffu, sum[mt][hh], 2);
                lrowv[mt][hh] = lrowv[mt][hh] * alpha[mt][hh] + sum[mt][hh];
            }

        // ---- O rescale + PV ----
#pragma unroll
        for (int mt = 0; mt < 2; mt++)
#pragma unroll
            for (int nt = 0; nt < 8; nt++) {
                o[mt][nt][0] *= alpha[mt][0];
                o[mt][nt][1] *= alpha[mt][0];
                o[mt][nt][2] *= alpha[mt][1];
                o[mt][nt][3] *= alpha[mt][1];
            }
#pragma unroll
        for (int kk = 0; kk < 2; kk++) {
            const int kbg = scb + kk * 16;
#pragma unroll
            for (int db = 0; db < 4; db++) {
                uint32_t bv4[4];
                ldsm4t(bv4, Vu + (uint32_t)((kbg + lrow) * 72 + db * 16 + lk8) * 2);
                mma16(o[0][db * 2    ], ap[0][kk], &bv4[0]);
                mma16(o[1][db * 2    ], ap[1][kk], &bv4[0]);
                mma16(o[0][db * 2 + 1], ap[0][kk], &bv4[2]);
                mma16(o[1][db * 2 + 1], ap[1][kk], &bv4[2]);
            }
        }
    }

    // ---- final combine: merge (O, m, l) across the two col-half warps ----
    float* cb = (float*)dsm;   // 64 x 68 f32 overlay (Q + K stage0 dead)
    __syncthreads();
    if (wc == 1) {
#pragma unroll
        for (int mt = 0; mt < 2; mt++) {
#pragma unroll
            for (int nt = 0; nt < 8; nt++) {
                int r0  = qr + mt * 16 + g;
                int col = nt * 8 + 2 * tig;
                *(float2*)&cb[r0 * 68 + col]       = make_float2(o[mt][nt][0], o[mt][nt][1]);
                *(float2*)&cb[(r0 + 8) * 68 + col] = make_float2(o[mt][nt][2], o[mt][nt][3]);
            }
            if (tig == 0) {
#pragma unroll
                for (int hh = 0; hh < 2; hh++) {
                    int row = qr + mt * 16 + g + hh * 8;
                    RM[row] = mrow[mt][hh];
                    RS[row] = lrowv[mt][hh];
                }
            }
        }
    }
    __syncthreads();
    if (wc == 0) {
#pragma unroll
        for (int mt = 0; mt < 2; mt++) {
            float sc0[2], sc1[2], inv[2];
#pragma unroll
            for (int hh = 0; hh < 2; hh++) {
                int row = qr + mt * 16 + g + hh * 8;
                float m1 = RM[row], l1 = RS[row];
                float M  = fmaxf(mrow[mt][hh], m1);
                sc0[hh] = ex2(mrow[mt][hh] - M);
                sc1[hh] = ex2(m1 - M);
                inv[hh] = 1.f / (lrowv[mt][hh] * sc0[hh] + l1 * sc1[hh]);
            }
            int r0 = qr + mt * 16 + g;
            float* p0 = out + ((size_t)(b * SEQ + q0 + r0    )) * HID + h * HD;
            float* p1 = out + ((size_t)(b * SEQ + q0 + r0 + 8)) * HID + h * HD;
#pragma unroll
            for (int nt = 0; nt < 8; nt++) {
                int col = nt * 8 + 2 * tig;
                float2 e0 = *(float2*)&cb[r0 * 68 + col];
                float2 e1 = *(float2*)&cb[(r0 + 8) * 68 + col];
                *(float2*)&p0[col] = make_float2(
                    (o[mt][nt][0] * sc0[0] + e0.x * sc1[0]) * inv[0],
                    (o[mt][nt][1] * sc0[0] + e0.y * sc1[0]) * inv[0]);
                *(float2*)&p1[col] = make_float2(
                    (o[mt][nt][2] * sc0[1] + e1.x * sc1[1]) * inv[1],
                    (o[mt][nt][3] * sc0[1] + e1.y * sc1[1]) * inv[1]);
            }
        }
    }
}

// ---------------------------------------------------------------------------
extern "C" void kernel_launch(void* const* d_in, const int* in_sizes, int n_in,
                              void* d_out, int out_size)
{
    const float* X    = (const float*)d_in[0];
    const float* mask = (const float*)d_in[1];
    const float* Wq   = (const float*)d_in[2];
    const float* bq   = (const float*)d_in[3];
    const float* Wk   = (const float*)d_in[4];
    const float* bk   = (const float*)d_in[5];
    const float* Wv   = (const float*)d_in[6];
    const float* bv   = (const float*)d_in[7];
    float* out = (float*)d_out;

    cudaFuncSetAttribute(flash_attn, cudaFuncAttributeMaxDynamicSharedMemorySize,
                         FA_SMEM);
    cudaFuncSetAttribute(qkv_gemm, cudaFuncAttributeMaxDynamicSharedMemorySize,
                         QKV_SMEM);

    const int XG = (Bsz*SEQ*HID) / 4;
    const int WG = (HID*HID) / 4;
    int cvt_blocks = (XG + 3 * WG + 255) / 256;
    to_half<<<cvt_blocks, 256>>>(X, Wq, Wk, Wv);

    dim3 g1(24, 32);
    qkv_gemm<<<g1, 512, QKV_SMEM>>>(bq, bk, bv);

    dim3 g2(32, NH, Bsz);
    flash_attn<<<g2, 128, FA_SMEM>>>(mask, out);
}

// round 14
// speedup vs baseline: 11.4081x; 1.0202x over previous
#include <cuda_runtime.h>
#include <cuda_fp16.h>
#include <math.h>
#include <stdint.h>

#define Bsz 4
#define SEQ 2048
#define HID 1024
#define NH 16
#define HD 64

// fp16 scratch
__device__ __half g_q[Bsz*NH*SEQ*HD];
__device__ __half g_k[Bsz*NH*SEQ*HD];
__device__ __half g_v[Bsz*NH*SEQ*HD];
__device__ __half g_xh[(size_t)Bsz*SEQ*HID];
__device__ __half g_wh[3*HID*HID];

// ---------------------------------------------------------------------------
__device__ __forceinline__ uint32_t sptr(const void* p) {
    return (uint32_t)__cvta_generic_to_shared(p);
}
__device__ __forceinline__ void ldsm4(uint32_t* r, uint32_t a) {
    asm volatile("ldmatrix.sync.aligned.m8n8.x4.shared.b16 {%0,%1,%2,%3}, [%4];"
        : "=r"(r[0]), "=r"(r[1]), "=r"(r[2]), "=r"(r[3]) : "r"(a));
}
__device__ __forceinline__ void ldsm4t(uint32_t* r, uint32_t a) {
    asm volatile("ldmatrix.sync.aligned.m8n8.x4.trans.shared.b16 {%0,%1,%2,%3}, [%4];"
        : "=r"(r[0]), "=r"(r[1]), "=r"(r[2]), "=r"(r[3]) : "r"(a));
}
__device__ __forceinline__ void mma16(float* c, const uint32_t* a, const uint32_t* b) {
    asm volatile(
        "mma.sync.aligned.m16n8k16.row.col.f32.f16.f16.f32 "
        "{%0,%1,%2,%3},{%4,%5,%6,%7},{%8,%9},{%0,%1,%2,%3};"
        : "+f"(c[0]), "+f"(c[1]), "+f"(c[2]), "+f"(c[3])
        : "r"(a[0]), "r"(a[1]), "r"(a[2]), "r"(a[3]), "r"(b[0]), "r"(b[1]));
}
// D = A*B + 0 (no accumulator init needed)
__device__ __forceinline__ void mma16z(float* c, const uint32_t* a, const uint32_t* b) {
    asm volatile(
        "mma.sync.aligned.m16n8k16.row.col.f32.f16.f16.f32 "
        "{%0,%1,%2,%3},{%4,%5,%6,%7},{%8,%9},{%10,%10,%10,%10};"
        : "=f"(c[0]), "=f"(c[1]), "=f"(c[2]), "=f"(c[3])
        : "r"(a[0]), "r"(a[1]), "r"(a[2]), "r"(a[3]), "r"(b[0]), "r"(b[1]),
          "f"(0.f));
}
__device__ __forceinline__ __half2 f22h(float x, float y) {
    return __float22half2_rn(make_float2(x, y));
}
__device__ __forceinline__ uint32_t f22hu(float x, float y) {
    __half2 h = __float22half2_rn(make_float2(x, y));
    return *(uint32_t*)&h;
}
__device__ __forceinline__ float ex2(float x) {
    float r; asm("ex2.approx.f32 %0, %1;" : "=f"(r) : "f"(x)); return r;
}
__device__ __forceinline__ void cpa16(uint32_t d, const void* s) {
    asm volatile("cp.async.cg.shared.global [%0], [%1], 16;" :: "r"(d), "l"(s));
}
__device__ __forceinline__ void cpa4(uint32_t d, const void* s) {
    asm volatile("cp.async.ca.shared.global [%0], [%1], 4;" :: "r"(d), "l"(s));
}
#define CP_COMMIT() asm volatile("cp.async.commit_group;")
#define CP_WAIT1()  asm volatile("cp.async.wait_group 1;")

// ---------------------------------------------------------------------------
// Kernel 0: convert X, Wq, Wk, Wv to fp16 scratch.
// ---------------------------------------------------------------------------
__global__ __launch_bounds__(256) void to_half(
    const float* __restrict__ X, const float* __restrict__ Wq,
    const float* __restrict__ Wk, const float* __restrict__ Wv)
{
    const int XG = (Bsz*SEQ*HID) / 4;
    const int WG = (HID*HID) / 4;
    int idx = blockIdx.x * blockDim.x + threadIdx.x;
    const float4* src;
    __half* dst;
    if (idx < XG)             { src = (const float4*)X  + idx;               dst = g_xh + (size_t)idx * 4; }
    else if (idx < XG + WG)   { src = (const float4*)Wq + (idx - XG);        dst = g_wh + (size_t)(idx - XG) * 4; }
    else if (idx < XG + 2*WG) { src = (const float4*)Wk + (idx - XG - WG);   dst = g_wh + (size_t)HID*HID + (size_t)(idx - XG - WG) * 4; }
    else if (idx < XG + 3*WG) { src = (const float4*)Wv + (idx - XG - 2*WG); dst = g_wh + (size_t)2*HID*HID + (size_t)(idx - XG - 2*WG) * 4; }
    else return;
    float4 v = *src;
    uint2 pack;
    pack.x = f22hu(v.x, v.y);
    pack.y = f22hu(v.z, v.w);
    *(uint2*)dst = pack;
}

// ---------------------------------------------------------------------------
// Kernel 1: fused QKV projection, fp16, BM=256 x BN=128, BK=32, 512 threads,
// 3-stage cp.async (wait_group 1), hoisted prefetch addressing.
// smem: As 3 x 20480B | Bs 3 x 8704B = 87552B
// ---------------------------------------------------------------------------
#define QKV_SMEM 87552

__global__ __launch_bounds__(512) void qkv_gemm(
    const float* __restrict__ bq, const float* __restrict__ bk,
    const float* __restrict__ bv)
{
    extern __shared__ __align__(16) __half qsm[];
    const uint32_t qb = sptr(qsm);
    const uint32_t BsBase = qb + 3 * 20480;

    const int tid  = threadIdx.x;
    const int warp = tid >> 5;
    const int lane = tid & 31;
    const int g    = lane >> 2;
    const int tig  = lane & 3;

    const int row0   = blockIdx.y * 256;
    const int colblk = blockIdx.x;
    const int sel    = colblk >> 3;
    const int ncol   = (colblk & 7) * 128;

    const __half* Wh  = g_wh + (size_t)sel * HID * HID;
    const float* bias = (sel == 0) ? bq : (sel == 1) ? bk : bv;
    __half*      dst  = (sel == 0) ? g_q : (sel == 1) ? g_k : g_v;

    const int wm = (warp >> 2) * 64;
    const int wn = (warp & 3) * 32;

    float acc[4][4][4];
#pragma unroll
    for (int i = 0; i < 4; i++)
#pragma unroll
        for (int j = 0; j < 4; j++)
#pragma unroll
            for (int k = 0; k < 4; k++) acc[i][j][k] = 0.f;

    const int lrow = ((lane >> 3) & 1) * 8 + (lane & 7);
    const int lk8  = (lane >> 4) * 8;

    // Hoisted prefetch addressing (loop-invariant per thread)
    const int ar  = tid >> 2;
    const int ac8 = (tid & 3) * 8;
    const int br  = tid >> 4;
    const int bc8 = (tid & 15) * 8;
    const uint32_t asm0 = (uint32_t)(ar * 40 + ac8) * 2;
    const uint32_t asm1 = (uint32_t)((ar + 128) * 40 + ac8) * 2;
    const uint32_t bsm0 = (uint32_t)(br * 136 + bc8) * 2;
    const __half* ag0 = g_xh + (size_t)(row0 + ar) * HID + ac8;
    const __half* ag1 = g_xh + (size_t)(row0 + ar + 128) * HID + ac8;
    const __half* bg0 = Wh + (size_t)br * HID + ncol + bc8;

    // prologue: stages 0 and 1
#pragma unroll
    for (int p = 0; p < 2; p++) {
        const int k0 = p * 32;
        const uint32_t AsB = qb + p * 20480;
        const uint32_t BsB = BsBase + p * 8704;
        cpa16(AsB + asm0, ag0 + k0);
        cpa16(AsB + asm1, ag1 + k0);
        cpa16(BsB + bsm0, bg0 + (size_t)k0 * HID);
        CP_COMMIT();
    }

    for (int ki = 0; ki < 32; ki++) {
        const int st = ki % 3;
        CP_WAIT1();
        __syncthreads();
        if (ki < 30) {
            const int k0 = (ki + 2) * 32;
            const int ns = (ki + 2) % 3;
            const uint32_t AsB = qb + ns * 20480;
            const uint32_t BsB = BsBase + ns * 8704;
            cpa16(AsB + asm0, ag0 + k0);
            cpa16(AsB + asm1, ag1 + k0);
            cpa16(BsB + bsm0, bg0 + (size_t)k0 * HID);
            CP_COMMIT();
        }
        const uint32_t AsB = qb + st * 20480;
        const uint32_t BsB = BsBase + st * 8704;

#pragma unroll
        for (int ks = 0; ks < 2; ks++) {
            const int kb = ks * 16;
            uint32_t a[4][4];
#pragma unroll
            for (int mt = 0; mt < 4; mt++)
                ldsm4(a[mt], AsB + (uint32_t)((wm + mt * 16 + lrow) * 40 + kb + lk8) * 2);
            uint32_t b[2][4];
#pragma unroll
            for (int nb = 0; nb < 2; nb++)
                ldsm4t(b[nb], BsB + (uint32_t)((kb + lrow) * 136 + wn + nb * 16 + lk8) * 2);
#pragma unroll
            for (int mt = 0; mt < 4; mt++)
#pragma unroll
                for (int nt = 0; nt < 4; nt++)
                    mma16(acc[mt][nt], a[mt], &b[nt >> 1][(nt & 1) * 2]);
        }
    }

    const int bidx = row0 >> 11;
#pragma unroll
    for (int mt = 0; mt < 4; mt++) {
        int r0 = row0 + wm + mt * 16 + g;
        int s0 = r0 & (SEQ - 1);
#pragma unroll
        for (int nt = 0; nt < 4; nt++) {
            int cc = wn + nt * 8 + 2 * tig;
            int h  = (ncol + cc) >> 6;
            int d  = (ncol + cc) & 63;
            float bf0 = bias[ncol + cc], bf1 = bias[ncol + cc + 1];
            __half* p = dst + (((size_t)bidx * NH + h) * SEQ + s0) * HD + d;
            *(__half2*)p            = f22h(acc[mt][nt][0] + bf0, acc[mt][nt][1] + bf1);
            *(__half2*)(p + 8 * HD) = f22h(acc[mt][nt][2] + bf0, acc[mt][nt][3] + bf1);
        }
    }
}

// ---------------------------------------------------------------------------
// Kernel 2: flash attention. Br=64, Bc=64, 128 threads, 4 warps (2 row x 2 col).
// Deferred-max split-k (warp-local softmax), in-register P, hoisted Q frags,
// 3-stage cp.async pipeline, zero-C S mma, ballot-skipped O rescale,
// hoisted prefetch addressing.
// Smem: Qs 9216 | K 3x9216 | V 3x9216 | Ms 3x64f | RM 128f | RS 128f = 66304B
// ---------------------------------------------------------------------------
#define FA_SMEM 66304

__global__ __launch_bounds__(128, 3) void flash_attn(
    const float* __restrict__ mask, float* __restrict__ out)
{
    extern __shared__ __align__(16) __half dsm[];
    const uint32_t sb  = sptr(dsm);
    const uint32_t KbB = sb + 9216;
    const uint32_t VbB = sb + 9216 + 27648;
    const uint32_t MsB = sb + 64512;
    float* Ms = (float*)((char*)dsm + 64512);
    float* RM = (float*)((char*)dsm + 65280);
    float* RS = (float*)((char*)dsm + 65792);

    const int b  = blockIdx.z;
    const int h  = blockIdx.y;
    const int q0 = blockIdx.x * 64;

    const int tid  = threadIdx.x;
    const int warp = tid >> 5;
    const int lane = tid & 31;
    const int g    = lane >> 2;
    const int tig  = lane & 3;
    const int wr   = warp >> 1;
    const int wc   = warp & 1;
    const int qr   = wr * 32;
    const int scb  = wc * 32;

    const int lrow = ((lane >> 3) & 1) * 8 + (lane & 7);
    const int lk8  = (lane >> 4) * 8;
    const int bn   = (lane >> 4) * 8 + (lane & 7);
    const int bk8  = ((lane >> 3) & 1) * 8;

    const __half* Qg = g_q + ((size_t)(b * NH + h) * SEQ) * HD;
    const __half* Kg = g_k + ((size_t)(b * NH + h) * SEQ) * HD;
    const __half* Vg = g_v + ((size_t)(b * NH + h) * SEQ) * HD;
    const float*  mk = mask + b * SEQ;

    // Hoisted prefetch addressing
    uint32_t psm[4];
    int      pge[4];
#pragma unroll
    for (int i = 0; i < 4; i++) {
        int lin = tid + i * 128;
        int r   = lin >> 3;
        int c8  = (lin & 7) * 8;
        psm[i] = (uint32_t)(r * 72 + c8) * 2;
        pge[i] = r * HD + c8;
    }

    // Prologue: group0 = Q + K0 + V0 + M0 ; group1 = K1 + V1 + M1
#pragma unroll
    for (int i = 0; i < 4; i++) {
        cpa16(sb  + psm[i], &Qg[(size_t)q0 * HD + pge[i]]);
        cpa16(KbB + psm[i], &Kg[pge[i]]);
        cpa16(VbB + psm[i], &Vg[pge[i]]);
    }
    if (tid < 64) cpa4(MsB + tid * 4, &mk[tid]);
    CP_COMMIT();
#pragma unroll
    for (int i = 0; i < 4; i++) {
        cpa16(KbB + 9216 + psm[i], &Kg[64 * HD + pge[i]]);
        cpa16(VbB + 9216 + psm[i], &Vg[64 * HD + pge[i]]);
    }
    if (tid < 64) cpa4(MsB + (64 + tid) * 4, &mk[64 + tid]);
    CP_COMMIT();

    CP_WAIT1();
    __syncthreads();

    // Hoist Q fragments (loop-invariant)
    uint32_t aq[2][4][4];
#pragma unroll
    for (int mt = 0; mt < 2; mt++)
#pragma unroll
        for (int kk = 0; kk < 4; kk++)
            ldsm4(aq[mt][kk], sb + (uint32_t)((qr + mt * 16 + lrow) * 72 + kk * 16 + lk8) * 2);

    float o[2][8][4];
#pragma unroll
    for (int mt = 0; mt < 2; mt++)
#pragma unroll
        for (int nt = 0; nt < 8; nt++)
#pragma unroll
            for (int j = 0; j < 4; j++) o[mt][nt][j] = 0.f;

    float mrow[2][2] = {{-1e30f, -1e30f}, {-1e30f, -1e30f}};
    float lrowv[2][2] = {{0.f, 0.f}, {0.f, 0.f}};
    const float C1  = 0.18033688011112042f;     // 0.125 * log2(e)
    const float L2E = 1.4426950408889634f;

    for (int it = 0; it < 32; it++) {
        const int st = it % 3;
        if (it > 0) {
            CP_WAIT1();
            __syncthreads();
        }
        if (it < 30) {
            const int ns = (it + 2) % 3;
            const int kc = (it + 2) * 64;
            const uint32_t kso = (uint32_t)(ns * 9216);
#pragma unroll
            for (int i = 0; i < 4; i++) {
                cpa16(KbB + kso + psm[i], &Kg[(size_t)kc * HD + pge[i]]);
                cpa16(VbB + kso + psm[i], &Vg[(size_t)kc * HD + pge[i]]);
            }
            if (tid < 64) cpa4(MsB + (ns * 64 + tid) * 4, &mk[kc + tid]);
            CP_COMMIT();
        }
        const uint32_t Ku = KbB + st * 9216;
        const uint32_t Vu = VbB + st * 9216;
        const float* Mb = Ms + st * 64;

        // ---- S = Q K^T : 32x32 per warp, kk=0 uses zero-C mma ----
        float s[2][4][4];
        {
            uint32_t bm[2][4];
            ldsm4(bm[0], Ku + (uint32_t)((scb      + bn) * 72 + bk8) * 2);
            ldsm4(bm[1], Ku + (uint32_t)((scb + 16 + bn) * 72 + bk8) * 2);
#pragma unroll
            for (int mt = 0; mt < 2; mt++)
#pragma unroll
                for (int nt = 0; nt < 4; nt++)
                    mma16z(s[mt][nt], aq[mt][0], &bm[nt >> 1][(nt & 1) * 2]);
        }
#pragma unroll
        for (int kk = 1; kk < 4; kk++) {
            const int kb = kk * 16;
            uint32_t bm[2][4];
            ldsm4(bm[0], Ku + (uint32_t)((scb      + bn) * 72 + kb + bk8) * 2);
            ldsm4(bm[1], Ku + (uint32_t)((scb + 16 + bn) * 72 + kb + bk8) * 2);
#pragma unroll
            for (int mt = 0; mt < 2; mt++)
#pragma unroll
                for (int nt = 0; nt < 4; nt++)
                    mma16(s[mt][nt], aq[mt][kk], &bm[nt >> 1][(nt & 1) * 2]);
        }

        // ---- warp-local scale + mask + row max ----
        float rm[2][2] = {{-1e30f, -1e30f}, {-1e30f, -1e30f}};
#pragma unroll
        for (int mt = 0; mt < 2; mt++)
#pragma unroll
            for (int nt = 0; nt < 4; nt++) {
                int col = scb + nt * 8 + 2 * tig;
                float mv0 = Mb[col] * L2E, mv1 = Mb[col + 1] * L2E;
                s[mt][nt][0] = s[mt][nt][0] * C1 + mv0;
                s[mt][nt][1] = s[mt][nt][1] * C1 + mv1;
                s[mt][nt][2] = s[mt][nt][2] * C1 + mv0;
                s[mt][nt][3] = s[mt][nt][3] * C1 + mv1;
                rm[mt][0] = fmaxf(rm[mt][0], fmaxf(s[mt][nt][0], s[mt][nt][1]));
                rm[mt][1] = fmaxf(rm[mt][1], fmaxf(s[mt][nt][2], s[mt][nt][3]));
            }
        float alpha[2][2];
#pragma unroll
        for (int mt = 0; mt < 2; mt++)
#pragma unroll
            for (int hh = 0; hh < 2; hh++) {
                rm[mt][hh] = fmaxf(rm[mt][hh], __shfl_xor_sync(0xffffffffu, rm[mt][hh], 1));
                rm[mt][hh] = fmaxf(rm[mt][hh], __shfl_xor_sync(0xffffffffu, rm[mt][hh], 2));
                float mn = fmaxf(mrow[mt][hh], rm[mt][hh]);
                alpha[mt][hh] = ex2(mrow[mt][hh] - mn);
                mrow[mt][hh] = mn;
            }

        // ---- exp2 + P pack + l update ----
        float sum[2][2] = {{0.f, 0.f}, {0.f, 0.f}};
        uint32_t ap[2][2][4];
#pragma unroll
        for (int mt = 0; mt < 2; mt++)
#pragma unroll
            for (int nt = 0; nt < 4; nt++) {
                float p0 = ex2(s[mt][nt][0] - mrow[mt][0]);
                float p1 = ex2(s[mt][nt][1] - mrow[mt][0]);
                float p2 = ex2(s[mt][nt][2] - mrow[mt][1]);
                float p3 = ex2(s[mt][nt][3] - mrow[mt][1]);
                sum[mt][0] += p0 + p1;
                sum[mt][1] += p2 + p3;
                const int kk = nt >> 1;
                if (nt & 1) {
                    ap[mt][kk][2] = f22hu(p0, p1);
                    ap[mt][kk][3] = f22hu(p2, p3);
                } else {
                    ap[mt][kk][0] = f22hu(p0, p1);
                    ap[mt][kk][1] = f22hu(p2, p3);
                }
            }
#pragma unroll
        for (int mt = 0; mt < 2; mt++)
#pragma unroll
            for (int hh = 0; hh < 2; hh++) {
                sum[mt][hh] += __shfl_xor_sync(0xffffffffu, sum[mt][hh], 1);
                sum[mt][hh] += __shfl_xor_sync(0xffffffffu, sum[mt][hh], 2);
                lrowv[mt][hh] = lrowv[mt][hh] * alpha[mt][hh] + sum[mt][hh];
            }

        // ---- O rescale, skipped when all alphas are exactly 1 ----
        bool need = (alpha[0][0] < 1.f) | (alpha[0][1] < 1.f)
                  | (alpha[1][0] < 1.f) | (alpha[1][1] < 1.f);
        if (__ballot_sync(0xffffffffu, need)) {
#pragma unroll
            for (int mt = 0; mt < 2; mt++)
#pragma unroll
                for (int nt = 0; nt < 8; nt++) {
                    o[mt][nt][0] *= alpha[mt][0];
                    o[mt][nt][1] *= alpha[mt][0];
                    o[mt][nt][2] *= alpha[mt][1];
                    o[mt][nt][3] *= alpha[mt][1];
                }
        }

        // ---- O += P V (k-half = this warp's S cols) ----
#pragma unroll
        for (int kk = 0; kk < 2; kk++) {
            const int kbg = scb + kk * 16;
#pragma unroll
            for (int db = 0; db < 4; db++) {
                uint32_t bv4[4];
                ldsm4t(bv4, Vu + (uint32_t)((kbg + lrow) * 72 + db * 16 + lk8) * 2);
                mma16(o[0][db * 2    ], ap[0][kk], &bv4[0]);
                mma16(o[1][db * 2    ], ap[1][kk], &bv4[0]);
                mma16(o[0][db * 2 + 1], ap[0][kk], &bv4[2]);
                mma16(o[1][db * 2 + 1], ap[1][kk], &bv4[2]);
            }
        }
    }

    // ---- final combine: merge (O, m, l) across the two col-half warps ----
    float* cb = (float*)dsm;
    __syncthreads();
    if (wc == 1) {
#pragma unroll
        for (int mt = 0; mt < 2; mt++) {
#pragma unroll
            for (int nt = 0; nt < 8; nt++) {
                int r0  = qr + mt * 16 + g;
                int col = nt * 8 + 2 * tig;
                *(float2*)&cb[r0 * 68 + col]       = make_float2(o[mt][nt][0], o[mt][nt][1]);
                *(float2*)&cb[(r0 + 8) * 68 + col] = make_float2(o[mt][nt][2], o[mt][nt][3]);
            }
            if (tig == 0) {
#pragma unroll
                for (int hh = 0; hh < 2; hh++) {
                    int row = qr + mt * 16 + g + hh * 8;
                    RM[row] = mrow[mt][hh];
                    RS[row] = lrowv[mt][hh];
                }
            }
        }
    }
    __syncthreads();
    if (wc == 0) {
#pragma unroll
        for (int mt = 0; mt < 2; mt++) {
            float sc0[2], sc1[2], inv[2];
#pragma unroll
            for (int hh = 0; hh < 2; hh++) {
                int row = qr + mt * 16 + g + hh * 8;
                float m1 = RM[row], l1 = RS[row];
                float M  = fmaxf(mrow[mt][hh], m1);
                sc0[hh] = ex2(mrow[mt][hh] - M);
                sc1[hh] = ex2(m1 - M);
                inv[hh] = 1.f / (lrowv[mt][hh] * sc0[hh] + l1 * sc1[hh]);
            }
            int r0 = qr + mt * 16 + g;
            float* p0 = out + ((size_t)(b * SEQ + q0 + r0    )) * HID + h * HD;
            float* p1 = out + ((size_t)(b * SEQ + q0 + r0 + 8)) * HID + h * HD;
#pragma unroll
            for (int nt = 0; nt < 8; nt++) {
                int col = nt * 8 + 2 * tig;
                float2 e0 = *(float2*)&cb[r0 * 68 + col];
                float2 e1 = *(float2*)&cb[(r0 + 8) * 68 + col];
                *(float2*)&p0[col] = make_float2(
                    (o[mt][nt][0] * sc0[0] + e0.x * sc1[0]) * inv[0],
                    (o[mt][nt][1] * sc0[0] + e0.y * sc1[0]) * inv[0]);
                *(float2*)&p1[col] = make_float2(
                    (o[mt][nt][2] * sc0[1] + e1.x * sc1[1]) * inv[1],
                    (o[mt][nt][3] * sc0[1] + e1.y * sc1[1]) * inv[1]);
            }
        }
    }
}

// ---------------------------------------------------------------------------
extern "C" void kernel_launch(void* const* d_in, const int* in_sizes, int n_in,
                              void* d_out, int out_size)
{
    const float* X    = (const float*)d_in[0];
    const float* mask = (const float*)d_in[1];
    const float* Wq   = (const float*)d_in[2];
    const float* bq   = (const float*)d_in[3];
    const float* Wk   = (const float*)d_in[4];
    const float* bk   = (const float*)d_in[5];
    const float* Wv   = (const float*)d_in[6];
    const float* bv   = (const float*)d_in[7];
    float* out = (float*)d_out;

    cudaFuncSetAttribute(flash_attn, cudaFuncAttributeMaxDynamicSharedMemorySize,
                         FA_SMEM);
    cudaFuncSetAttribute(qkv_gemm, cudaFuncAttributeMaxDynamicSharedMemorySize,
                         QKV_SMEM);

    const int XG = (Bsz*SEQ*HID) / 4;
    const int WG = (HID*HID) / 4;
    int cvt_blocks = (XG + 3 * WG + 255) / 256;
    to_half<<<cvt_blocks, 256>>>(X, Wq, Wk, Wv);

    dim3 g1(24, 32);
    qkv_gemm<<<g1, 512, QKV_SMEM>>>(bq, bk, bv);

    dim3 g2(32, NH, Bsz);
    flash_attn<<<g2, 128, FA_SMEM>>>(mask, out);
}